// round 5
// baseline (speedup 1.0000x reference)
#include <cuda_runtime.h>
#include <cuda_bf16.h>
#include <cuda_fp16.h>
#include <float.h>
#include <stdint.h>

// ---------------------------------------------------------------------------
// Problem constants
// ---------------------------------------------------------------------------
#define BATCH   8
#define NP      4224
#define NSEQ    4223
#define TEXTL   128
#define IMGDIM  64
#define NHEAD   16
#define DHEAD   64
#define DIMC    1024
#define TRIPLE  3072
#define MROWS   (BATCH*NP)    // 33792
#define KTOT    1024
#define BK      32
#define NCHUNK  (KTOT / BK)

// Scratch (device globals — no allocation allowed)
__device__ float          g_qkv   [(size_t)BATCH * NP * TRIPLE];
__device__ float          g_attn  [(size_t)BATCH * NP * DIMC];
__device__ __nv_bfloat16  g_ah    [(size_t)MROWS * KTOT];       // A hi
__device__ __nv_bfloat16  g_al    [(size_t)MROWS * KTOT];       // A lo
__device__ __nv_bfloat16  g_bh_qkv[(size_t)TRIPLE * KTOT];
__device__ __nv_bfloat16  g_bl_qkv[(size_t)TRIPLE * KTOT];
__device__ __nv_bfloat16  g_bh_out[(size_t)DIMC * KTOT];
__device__ __nv_bfloat16  g_bl_out[(size_t)DIMC * KTOT];
__device__ uint8_t        g_mask  [BATCH * TEXTL];

// ---------------------------------------------------------------------------
// PTX helpers (baseline PTX only — compute_103 virtual arch)
// ---------------------------------------------------------------------------
__device__ __forceinline__ uint32_t smem_u32(const void* p) {
    uint32_t a;
    asm("{ .reg .u64 t; cvta.to.shared.u64 t, %1; cvt.u32.u64 %0, t; }" : "=r"(a) : "l"(p));
    return a;
}
__device__ __forceinline__ void mma16816(float d[4],
    uint32_t a0, uint32_t a1, uint32_t a2, uint32_t a3, uint32_t b0, uint32_t b1)
{
    asm volatile(
        "mma.sync.aligned.m16n8k16.row.col.f32.bf16.bf16.f32 "
        "{%0,%1,%2,%3},{%4,%5,%6,%7},{%8,%9},{%0,%1,%2,%3};\n"
        : "+f"(d[0]), "+f"(d[1]), "+f"(d[2]), "+f"(d[3])
        : "r"(a0), "r"(a1), "r"(a2), "r"(a3), "r"(b0), "r"(b1));
}
__device__ __forceinline__ void ldsm_x4(uint32_t r[4], uint32_t addr)
{
    asm volatile("ldmatrix.sync.aligned.m8n8.x4.shared.b16 {%0,%1,%2,%3}, [%4];"
                 : "=r"(r[0]), "=r"(r[1]), "=r"(r[2]), "=r"(r[3]) : "r"(addr));
}
__device__ __forceinline__ void cp_async16(uint32_t dst, const void* src)
{
    asm volatile("cp.async.cg.shared.global [%0], [%1], 16;" :: "r"(dst), "l"(src) : "memory");
}
#define CP_COMMIT()  asm volatile("cp.async.commit_group;" ::: "memory")
#define CP_WAIT(N)   asm volatile("cp.async.wait_group %0;" :: "n"(N) : "memory")

// ---------------------------------------------------------------------------
// Mask normalization (bool mask may arrive as int32 / float32 / uint8)
// ---------------------------------------------------------------------------
__global__ void normalize_mask_kernel(const void* __restrict__ mask_raw)
{
    __shared__ int cls;
    const uint32_t* w = (const uint32_t*)mask_raw;
    const uint8_t*  c = (const uint8_t*)mask_raw;
    if (threadIdx.x == 0) {
        bool all_int = true, all_f32 = true;
        for (int i = 0; i < 256; i++) {
            uint32_t v = w[i];
            if (v != 0u && v != 1u)          all_int = false;
            if (v != 0u && v != 0x3F800000u) all_f32 = false;
        }
        cls = (all_int || all_f32) ? 0 : 1;
    }
    __syncthreads();
    for (int i = threadIdx.x; i < BATCH * TEXTL; i += blockDim.x)
        g_mask[i] = (cls == 0) ? (w[i] != 0u) : (c[i] != 0u);
}

// ---------------------------------------------------------------------------
// Split helpers: fp32 -> (hi, lo) bf16
// ---------------------------------------------------------------------------
__device__ __forceinline__ void split1(float v, __nv_bfloat16& h, __nv_bfloat16& l)
{
    h = __float2bfloat16_rn(v);
    l = __float2bfloat16_rn(v - __bfloat162float(h));
}

// A-side split: src has NSEQ real rows per batch (PAD=true) or full MROWS rows.
template <bool PAD>
__global__ __launch_bounds__(256) void split_a_kernel(const float* __restrict__ src)
{
    int idx = blockIdx.x * 256 + threadIdx.x;     // one float4 per thread
    int m   = idx >> 8;
    int c4  = idx & 255;
    float4 v = make_float4(0.f, 0.f, 0.f, 0.f);
    if (PAD) {
        int b = m / NP, t = m - b * NP;
        if (t < NSEQ) v = *(const float4*)&src[((size_t)(b * NSEQ + t)) * KTOT + c4 * 4];
    } else {
        v = *(const float4*)&src[(size_t)m * KTOT + c4 * 4];
    }
    __nv_bfloat16 h[4], l[4];
    split1(v.x, h[0], l[0]); split1(v.y, h[1], l[1]);
    split1(v.z, h[2], l[2]); split1(v.w, h[3], l[3]);
    size_t off = (size_t)m * KTOT + c4 * 4;
    *(uint2*)&g_ah[off] = *(uint2*)h;
    *(uint2*)&g_al[off] = *(uint2*)l;
}

// W-side: transpose + split.  src [K][C] fp32 -> dh/dl [C][K] bf16
__global__ __launch_bounds__(256) void split_w_kernel(
    const float* __restrict__ src, __nv_bfloat16* __restrict__ dh,
    __nv_bfloat16* __restrict__ dl, int K, int C)
{
    __shared__ float tile[32][33];
    int c0 = blockIdx.x * 32, k0 = blockIdx.y * 32;
    int x = threadIdx.x, y = threadIdx.y;
#pragma unroll
    for (int i = 0; i < 32; i += 8)
        tile[y + i][x] = src[(size_t)(k0 + y + i) * C + c0 + x];
    __syncthreads();
#pragma unroll
    for (int i = 0; i < 32; i += 8) {
        float v = tile[x][y + i];
        __nv_bfloat16 h, l;
        split1(v, h, l);
        size_t off = (size_t)(c0 + y + i) * K + k0 + x;
        dh[off] = h; dl[off] = l;
    }
}

// ---------------------------------------------------------------------------
// bf16x3 tensor-core GEMM:  C[M,N] = A[M,1024] @ B[N,1024]^T   (pre-split bf16)
// CTA 128x128, BK=32, 256 threads (8 warps, 2x4), warp tile 64x32, m16n8k16.
// cp.async double-buffered SMEM, ldmatrix fragment loads, 2 CTAs/SM.
// ---------------------------------------------------------------------------
#define LSTRIDE   40                              // bf16 elems per smem row (80B)
#define ARR_ELEMS (128 * LSTRIDE)                 // 5120
#define STAGE_ELEMS (4 * ARR_ELEMS)
#define SMEM_GEMM (2 * STAGE_ELEMS * 2)           // 81920 bytes

template <int NSTRIDE, bool TRIM>
__global__ __launch_bounds__(256, 2)
void gemm_bf16x3_kernel(const __nv_bfloat16* __restrict__ Ahg,
                        const __nv_bfloat16* __restrict__ Alg,
                        const __nv_bfloat16* __restrict__ Bhg,
                        const __nv_bfloat16* __restrict__ Blg,
                        float* __restrict__ C)
{
    extern __shared__ __nv_bfloat16 sm[];
    const int tid  = threadIdx.x;
    const int bn   = blockIdx.x;
    const int bm   = blockIdx.y;
    const int warp = tid >> 5;
    const int lane = tid & 31;
    const int wm   = warp >> 2;
    const int wn   = warp & 3;
    const int g    = lane >> 2;
    const int t4   = lane & 3;

    float acc[4][4][4];
#pragma unroll
    for (int mi = 0; mi < 4; mi++)
#pragma unroll
        for (int ni = 0; ni < 4; ni++)
#pragma unroll
            for (int r = 0; r < 4; r++) acc[mi][ni][r] = 0.f;

    const __nv_bfloat16* srcs[4] = { Ahg, Alg, Bhg, Blg };

    auto issue = [&](int kc) {
        const int buf = kc & 1;
        const int k0  = kc * BK;
#pragma unroll
        for (int arr = 0; arr < 4; arr++) {
            const __nv_bfloat16* base = srcs[arr];
            const size_t rbase = (arr < 2) ? (size_t)bm * 128 : (size_t)bn * 128;
            __nv_bfloat16* stg = sm + (buf * 4 + arr) * ARR_ELEMS;
#pragma unroll
            for (int q = 0; q < 2; q++) {
                int idx = tid * 2 + q;            // 0..511
                int row = idx >> 2, seg = idx & 3;
                cp_async16(smem_u32(stg + row * LSTRIDE + seg * 8),
                           base + (rbase + row) * KTOT + k0 + seg * 8);
            }
        }
        CP_COMMIT();
    };

    issue(0);

    for (int kc = 0; kc < NCHUNK; kc++) {
        const int buf = kc & 1;
        if (kc + 1 < NCHUNK) { issue(kc + 1); CP_WAIT(1); }
        else                 { CP_WAIT(0); }
        __syncthreads();

        const uint32_t aAh = smem_u32(sm + (buf * 4 + 0) * ARR_ELEMS);
        const uint32_t aAl = smem_u32(sm + (buf * 4 + 1) * ARR_ELEMS);
        const uint32_t aBh = smem_u32(sm + (buf * 4 + 2) * ARR_ELEMS);
        const uint32_t aBl = smem_u32(sm + (buf * 4 + 3) * ARR_ELEMS);

#pragma unroll
        for (int ks = 0; ks < 2; ks++) {
            // B fragments: 2 ni-pairs, hi+lo
            uint32_t bh[2][4], bl[2][4];
#pragma unroll
            for (int nip = 0; nip < 2; nip++) {
                int row  = wn * 32 + nip * 16 + ((lane >> 4) << 3) + (lane & 7);
                int colb = ((lane >> 3) & 1) * 16 + ks * 32;
                ldsm_x4(bh[nip], aBh + row * 80 + colb);
                ldsm_x4(bl[nip], aBl + row * 80 + colb);
            }
            // A fragments in 2 halves to bound register pressure
#pragma unroll
            for (int mh = 0; mh < 2; mh++) {
                uint32_t ah[2][4], al[2][4];
#pragma unroll
                for (int m2 = 0; m2 < 2; m2++) {
                    int mi   = mh * 2 + m2;
                    int row  = wm * 64 + mi * 16 + (lane & 15);
                    int cola = (lane >> 4) * 16 + ks * 32;
                    ldsm_x4(ah[m2], aAh + row * 80 + cola);
                    ldsm_x4(al[m2], aAl + row * 80 + cola);
                }
#pragma unroll
                for (int m2 = 0; m2 < 2; m2++) {
                    int mi = mh * 2 + m2;
#pragma unroll
                    for (int nip = 0; nip < 2; nip++) {
#pragma unroll
                        for (int s = 0; s < 2; s++) {
                            int ni = nip * 2 + s;
                            uint32_t b0h = bh[nip][2*s], b1h = bh[nip][2*s+1];
                            uint32_t b0l = bl[nip][2*s], b1l = bl[nip][2*s+1];
                            mma16816(acc[mi][ni], ah[m2][0],ah[m2][1],ah[m2][2],ah[m2][3], b0h,b1h);
                            mma16816(acc[mi][ni], ah[m2][0],ah[m2][1],ah[m2][2],ah[m2][3], b0l,b1l);
                            mma16816(acc[mi][ni], al[m2][0],al[m2][1],al[m2][2],al[m2][3], b0h,b1h);
                        }
                    }
                }
            }
        }
        __syncthreads();
    }

    // ---- epilogue ----
#pragma unroll
    for (int mi = 0; mi < 4; mi++) {
#pragma unroll
        for (int half = 0; half < 2; half++) {
            int m = bm * 128 + wm * 64 + mi * 16 + g + half * 8;
            float* dst = nullptr;
            if (TRIM) {
                int b = m / NP, t = m - b * NP;
                if (t < NSEQ) dst = &C[((size_t)(b * NSEQ + t)) * NSTRIDE];
            } else {
                dst = &C[(size_t)m * NSTRIDE];
            }
            if (dst) {
                int ncol = bn * 128 + wn * 32 + t4 * 2;
#pragma unroll
                for (int ni = 0; ni < 4; ni++) {
                    float2 v = make_float2(acc[mi][ni][half * 2], acc[mi][ni][half * 2 + 1]);
                    *(float2*)&dst[ncol + ni * 8] = v;
                }
            }
        }
    }
}

// ---------------------------------------------------------------------------
// Text attention: per (b,h), 128 queries x 128 keys, causal. fp32.
// ---------------------------------------------------------------------------
__global__ __launch_bounds__(128) void text_attn_kernel()
{
    extern __shared__ float smf[];
    float* KV = smf;
    float* S  = smf + 128 * 64;

    const int bh = blockIdx.x;
    const int b  = bh / NHEAD;
    const int h  = bh - b * NHEAD;
    const int i  = threadIdx.x;

    for (int idx = threadIdx.x; idx < 128 * 64 / 4; idx += 128) {
        int t = idx >> 4, c4 = idx & 15;
        *(float4*)&KV[t * 64 + c4 * 4] =
            *(const float4*)&g_qkv[((size_t)(b * NP + t)) * TRIPLE + DIMC + h * DHEAD + c4 * 4];
    }
    __syncthreads();

    float q[64];
    {
        const float* qp = &g_qkv[((size_t)(b * NP + i)) * TRIPLE + h * DHEAD];
#pragma unroll
        for (int d = 0; d < 64; d++) q[d] = qp[d] * 0.125f;
    }

    float mx = -FLT_MAX;
    for (int j = 0; j <= i; j++) {
        const float* kp = &KV[j * 64];
        float s0 = 0.f, s1 = 0.f, s2 = 0.f, s3 = 0.f;
#pragma unroll
        for (int d = 0; d < 64; d += 4) {
            s0 += q[d+0] * kp[d+0]; s1 += q[d+1] * kp[d+1];
            s2 += q[d+2] * kp[d+2]; s3 += q[d+3] * kp[d+3];
        }
        float s = (s0 + s1) + (s2 + s3);
        S[i * 128 + j] = s;
        mx = fmaxf(mx, s);
    }
    float sum = 0.f;
    for (int j = 0; j <= i; j++) {
        float p = __expf(S[i * 128 + j] - mx);
        S[i * 128 + j] = p;
        sum += p;
    }
    __syncthreads();

    for (int idx = threadIdx.x; idx < 128 * 64 / 4; idx += 128) {
        int t = idx >> 4, c4 = idx & 15;
        *(float4*)&KV[t * 64 + c4 * 4] =
            *(const float4*)&g_qkv[((size_t)(b * NP + t)) * TRIPLE + 2 * DIMC + h * DHEAD + c4 * 4];
    }
    __syncthreads();

    float o[64];
#pragma unroll
    for (int d = 0; d < 64; d++) o[d] = 0.f;
    for (int j = 0; j <= i; j++) {
        float p = S[i * 128 + j];
        const float* vp = &KV[j * 64];
#pragma unroll
        for (int d = 0; d < 64; d++) o[d] += p * vp[d];
    }
    float inv = 1.f / sum;
    float* op = &g_attn[((size_t)(b * NP + i)) * DIMC + h * DHEAD];
#pragma unroll
    for (int d = 0; d < 64; d++) op[d] = o[d] * inv;
}

// ---------------------------------------------------------------------------
// Image (axial) attention — fp16 smem version (halves smem: 4 blocks/SM).
// per (b,h,imgrow): 64 queries x (128 text keys masked + <=64 row keys causal).
// ---------------------------------------------------------------------------
#define SMEM_IMG ((192 * 64 + 64 * 192) * 2)   // 49152 bytes

__global__ __launch_bounds__(64) void img_attn_kernel()
{
    extern __shared__ __half smh[];
    __half* KV = smh;                 // 192 x 64 fp16
    __half* S  = smh + 192 * 64;      // 64 x 192 fp16
    __shared__ uint8_t smask[TEXTL];

    const int bid = blockIdx.x;
    const int xr  = bid & 63;
    const int h   = (bid >> 6) & 15;
    const int b   = bid >> 10;
    const int i   = threadIdx.x;

    for (int j = threadIdx.x; j < TEXTL; j += 64) smask[j] = g_mask[b * TEXTL + j];

    // load K fp32 -> fp16 smem
    for (int idx = threadIdx.x; idx < 192 * 16; idx += 64) {
        int r = idx >> 4, c4 = idx & 15;
        int t = (r < TEXTL) ? r : (TEXTL + xr * 64 + (r - TEXTL));
        float4 v = *(const float4*)&g_qkv[((size_t)(b * NP + t)) * TRIPLE + DIMC + h * DHEAD + c4 * 4];
        __half2* dst = (__half2*)&KV[r * 64 + c4 * 4];
        dst[0] = __floats2half2_rn(v.x, v.y);
        dst[1] = __floats2half2_rn(v.z, v.w);
    }
    __syncthreads();

    float q[64];
    {
        const int tq = TEXTL + xr * 64 + i;
        const float* qp = &g_qkv[((size_t)(b * NP + tq)) * TRIPLE + h * DHEAD];
#pragma unroll
        for (int d = 0; d < 64; d++) q[d] = qp[d] * 0.125f;
    }

    auto dot192 = [&](int r) -> float {
        const uint4* kp = (const uint4*)&KV[r * 64];
        float s0 = 0.f, s1 = 0.f, s2 = 0.f, s3 = 0.f;
#pragma unroll
        for (int w = 0; w < 8; w++) {
            uint4 u = kp[w];
            float2 f0 = __half22float2(*(__half2*)&u.x);
            float2 f1 = __half22float2(*(__half2*)&u.y);
            float2 f2 = __half22float2(*(__half2*)&u.z);
            float2 f3 = __half22float2(*(__half2*)&u.w);
            int d = w * 8;
            s0 += q[d+0] * f0.x; s1 += q[d+1] * f0.y;
            s2 += q[d+2] * f1.x; s3 += q[d+3] * f1.y;
            s0 += q[d+4] * f2.x; s1 += q[d+5] * f2.y;
            s2 += q[d+6] * f3.x; s3 += q[d+7] * f3.y;
        }
        return (s0 + s1) + (s2 + s3);
    };

    float mx = -FLT_MAX;
    float sraw[1];  (void)sraw;
    // text keys (masked) — store raw scores as fp16 is unsafe for -inf; use sentinel
    for (int j = 0; j < TEXTL; j++) {
        float s = smask[j] ? dot192(j) : -65000.f;   // fp16-representable "-inf"
        S[i * 192 + j] = __float2half_rn(s);
        mx = fmaxf(mx, s);
    }
    for (int j = 0; j <= i; j++) {
        float s = dot192(TEXTL + j);
        S[i * 192 + TEXTL + j] = __float2half_rn(s);
        mx = fmaxf(mx, s);
    }

    float sum = 0.f;
    for (int j = 0; j < TEXTL; j++) {
        float s = __half2float(S[i * 192 + j]);
        float p = (s < -60000.f) ? 0.f : __expf(s - mx);
        S[i * 192 + j] = __float2half_rn(p);
        sum += p;
    }
    for (int j = 0; j <= i; j++) {
        float p = __expf(__half2float(S[i * 192 + TEXTL + j]) - mx);
        S[i * 192 + TEXTL + j] = __float2half_rn(p);
        sum += p;
    }
    __syncthreads();

    // load V over KV
    for (int idx = threadIdx.x; idx < 192 * 16; idx += 64) {
        int r = idx >> 4, c4 = idx & 15;
        int t = (r < TEXTL) ? r : (TEXTL + xr * 64 + (r - TEXTL));
        float4 v = *(const float4*)&g_qkv[((size_t)(b * NP + t)) * TRIPLE + 2 * DIMC + h * DHEAD + c4 * 4];
        __half2* dst = (__half2*)&KV[r * 64 + c4 * 4];
        dst[0] = __floats2half2_rn(v.x, v.y);
        dst[1] = __floats2half2_rn(v.z, v.w);
    }
    __syncthreads();

    float o[64];
#pragma unroll
    for (int d = 0; d < 64; d++) o[d] = 0.f;

    auto accum = [&](int r, float p) {
        const uint4* vp = (const uint4*)&KV[r * 64];
#pragma unroll
        for (int w = 0; w < 8; w++) {
            uint4 u = vp[w];
            float2 f0 = __half22float2(*(__half2*)&u.x);
            float2 f1 = __half22float2(*(__half2*)&u.y);
            float2 f2 = __half22float2(*(__half2*)&u.z);
            float2 f3 = __half22float2(*(__half2*)&u.w);
            int d = w * 8;
            o[d+0] += p * f0.x; o[d+1] += p * f0.y;
            o[d+2] += p * f1.x; o[d+3] += p * f1.y;
            o[d+4] += p * f2.x; o[d+5] += p * f2.y;
            o[d+6] += p * f3.x; o[d+7] += p * f3.y;
        }
    };

    for (int j = 0; j < TEXTL; j++)
        accum(j, __half2float(S[i * 192 + j]));
    for (int j = 0; j <= i; j++)
        accum(TEXTL + j, __half2float(S[i * 192 + TEXTL + j]));

    float inv = 1.f / sum;
    const int tq = TEXTL + xr * 64 + i;
    float* op = &g_attn[((size_t)(b * NP + tq)) * DIMC + h * DHEAD];
#pragma unroll
    for (int d = 0; d < 64; d++) op[d] = o[d] * inv;
}

// ---------------------------------------------------------------------------
// Launch
// ---------------------------------------------------------------------------
extern "C" void kernel_launch(void* const* d_in, const int* in_sizes, int n_in,
                              void* d_out, int out_size)
{
    const float* x     = nullptr;
    const void*  mask  = nullptr;
    const float* w_qkv = nullptr;
    const float* w_out = nullptr;
    for (int i = 0; i < n_in; i++) {
        long long sz = in_sizes[i];
        if      (sz == (long long)BATCH * NSEQ * DIMC) x     = (const float*)d_in[i];
        else if (sz == BATCH * TEXTL)                  mask  = d_in[i];
        else if (sz == (long long)DIMC * TRIPLE)       w_qkv = (const float*)d_in[i];
        else if (sz == (long long)DIMC * DIMC)         w_out = (const float*)d_in[i];
    }
    float* out = (float*)d_out;

    __nv_bfloat16 *ah, *al, *bhq, *blq, *bho, *blo;
    float *attn, *qkv;
    cudaGetSymbolAddress((void**)&ah,  g_ah);
    cudaGetSymbolAddress((void**)&al,  g_al);
    cudaGetSymbolAddress((void**)&bhq, g_bh_qkv);
    cudaGetSymbolAddress((void**)&blq, g_bl_qkv);
    cudaGetSymbolAddress((void**)&bho, g_bh_out);
    cudaGetSymbolAddress((void**)&blo, g_bl_out);
    cudaGetSymbolAddress((void**)&attn, g_attn);
    cudaGetSymbolAddress((void**)&qkv,  g_qkv);

    const int SMEM_TXT = 98304;
    cudaFuncSetAttribute(text_attn_kernel, cudaFuncAttributeMaxDynamicSharedMemorySize, SMEM_TXT);
    cudaFuncSetAttribute(img_attn_kernel,  cudaFuncAttributeMaxDynamicSharedMemorySize, SMEM_IMG);
    cudaFuncSetAttribute(gemm_bf16x3_kernel<TRIPLE, false>,
                         cudaFuncAttributeMaxDynamicSharedMemorySize, SMEM_GEMM);
    cudaFuncSetAttribute(gemm_bf16x3_kernel<DIMC, true>,
                         cudaFuncAttributeMaxDynamicSharedMemorySize, SMEM_GEMM);

    normalize_mask_kernel<<<1, 256>>>(mask);
    split_w_kernel<<<dim3(TRIPLE / 32, KTOT / 32), dim3(32, 8)>>>(w_qkv, bhq, blq, KTOT, TRIPLE);
    split_w_kernel<<<dim3(DIMC / 32,   KTOT / 32), dim3(32, 8)>>>(w_out, bho, blo, KTOT, DIMC);
    split_a_kernel<true><<<MROWS, 256>>>(x);

    dim3 g1(TRIPLE / 128, MROWS / 128);  // 24 x 264
    gemm_bf16x3_kernel<TRIPLE, false><<<g1, 256, SMEM_GEMM>>>(ah, al, bhq, blq, qkv);

    text_attn_kernel<<<BATCH * NHEAD, 128, SMEM_TXT>>>();
    img_attn_kernel<<<BATCH * NHEAD * IMGDIM, 64, SMEM_IMG>>>();

    split_a_kernel<false><<<MROWS, 256>>>(attn);

    dim3 g2(DIMC / 128, MROWS / 128);    // 8 x 264
    gemm_bf16x3_kernel<DIMC, true><<<g2, 256, SMEM_GEMM>>>(ah, al, bho, blo, out);
}

// round 6
// speedup vs baseline: 1.5783x; 1.5783x over previous
#include <cuda_runtime.h>
#include <cuda_bf16.h>
#include <cuda_fp16.h>
#include <float.h>
#include <stdint.h>

// ---------------------------------------------------------------------------
// Problem constants
// ---------------------------------------------------------------------------
#define BATCH   8
#define NP      4224
#define NSEQ    4223
#define TEXTL   128
#define IMGDIM  64
#define NHEAD   16
#define DHEAD   64
#define DIMC    1024
#define TRIPLE  3072
#define MROWS   (BATCH*NP)    // 33792
#define KTOT    1024
#define BK      32
#define NCHUNK  (KTOT / BK)

// Scratch (device globals — no allocation allowed)
__device__ float          g_qkv   [(size_t)BATCH * NP * TRIPLE];
__device__ float          g_attn  [(size_t)BATCH * NP * DIMC];
__device__ __nv_bfloat16  g_ah    [(size_t)MROWS * KTOT];       // A hi
__device__ __nv_bfloat16  g_al    [(size_t)MROWS * KTOT];       // A lo
__device__ __nv_bfloat16  g_bh_qkv[(size_t)TRIPLE * KTOT];
__device__ __nv_bfloat16  g_bl_qkv[(size_t)TRIPLE * KTOT];
__device__ __nv_bfloat16  g_bh_out[(size_t)DIMC * KTOT];
__device__ __nv_bfloat16  g_bl_out[(size_t)DIMC * KTOT];
__device__ uint8_t        g_mask  [BATCH * TEXTL];

// ---------------------------------------------------------------------------
// PTX helpers (baseline PTX only — compute_103 virtual arch)
// ---------------------------------------------------------------------------
__device__ __forceinline__ uint32_t smem_u32(const void* p) {
    uint32_t a;
    asm("{ .reg .u64 t; cvta.to.shared.u64 t, %1; cvt.u32.u64 %0, t; }" : "=r"(a) : "l"(p));
    return a;
}
__device__ __forceinline__ void mma16816(float d[4],
    uint32_t a0, uint32_t a1, uint32_t a2, uint32_t a3, uint32_t b0, uint32_t b1)
{
    asm volatile(
        "mma.sync.aligned.m16n8k16.row.col.f32.bf16.bf16.f32 "
        "{%0,%1,%2,%3},{%4,%5,%6,%7},{%8,%9},{%0,%1,%2,%3};\n"
        : "+f"(d[0]), "+f"(d[1]), "+f"(d[2]), "+f"(d[3])
        : "r"(a0), "r"(a1), "r"(a2), "r"(a3), "r"(b0), "r"(b1));
}
__device__ __forceinline__ void ldsm_x4(uint32_t r[4], uint32_t addr)
{
    asm volatile("ldmatrix.sync.aligned.m8n8.x4.shared.b16 {%0,%1,%2,%3}, [%4];"
                 : "=r"(r[0]), "=r"(r[1]), "=r"(r[2]), "=r"(r[3]) : "r"(addr));
}
__device__ __forceinline__ void cp_async16(uint32_t dst, const void* src)
{
    asm volatile("cp.async.cg.shared.global [%0], [%1], 16;" :: "r"(dst), "l"(src) : "memory");
}
#define CP_COMMIT()  asm volatile("cp.async.commit_group;" ::: "memory")
#define CP_WAIT(N)   asm volatile("cp.async.wait_group %0;" :: "n"(N) : "memory")

// ---------------------------------------------------------------------------
// Mask normalization (bool mask may arrive as int32 / float32 / uint8)
// ---------------------------------------------------------------------------
__global__ void normalize_mask_kernel(const void* __restrict__ mask_raw)
{
    __shared__ int cls;
    const uint32_t* w = (const uint32_t*)mask_raw;
    const uint8_t*  c = (const uint8_t*)mask_raw;
    if (threadIdx.x == 0) {
        bool all_int = true, all_f32 = true;
        for (int i = 0; i < 256; i++) {
            uint32_t v = w[i];
            if (v != 0u && v != 1u)          all_int = false;
            if (v != 0u && v != 0x3F800000u) all_f32 = false;
        }
        cls = (all_int || all_f32) ? 0 : 1;
    }
    __syncthreads();
    for (int i = threadIdx.x; i < BATCH * TEXTL; i += blockDim.x)
        g_mask[i] = (cls == 0) ? (w[i] != 0u) : (c[i] != 0u);
}

// ---------------------------------------------------------------------------
// Split helpers: fp32 -> (hi, lo) bf16
// ---------------------------------------------------------------------------
__device__ __forceinline__ void split1(float v, __nv_bfloat16& h, __nv_bfloat16& l)
{
    h = __float2bfloat16_rn(v);
    l = __float2bfloat16_rn(v - __bfloat162float(h));
}

template <bool PAD>
__global__ __launch_bounds__(256) void split_a_kernel(const float* __restrict__ src)
{
    int idx = blockIdx.x * 256 + threadIdx.x;     // one float4 per thread
    int m   = idx >> 8;
    int c4  = idx & 255;
    float4 v = make_float4(0.f, 0.f, 0.f, 0.f);
    if (PAD) {
        int b = m / NP, t = m - b * NP;
        if (t < NSEQ) v = *(const float4*)&src[((size_t)(b * NSEQ + t)) * KTOT + c4 * 4];
    } else {
        v = *(const float4*)&src[(size_t)m * KTOT + c4 * 4];
    }
    __nv_bfloat16 h[4], l[4];
    split1(v.x, h[0], l[0]); split1(v.y, h[1], l[1]);
    split1(v.z, h[2], l[2]); split1(v.w, h[3], l[3]);
    size_t off = (size_t)m * KTOT + c4 * 4;
    *(uint2*)&g_ah[off] = *(uint2*)h;
    *(uint2*)&g_al[off] = *(uint2*)l;
}

// W-side: transpose + split.  src [K][C] fp32 -> dh/dl [C][K] bf16
__global__ __launch_bounds__(256) void split_w_kernel(
    const float* __restrict__ src, __nv_bfloat16* __restrict__ dh,
    __nv_bfloat16* __restrict__ dl, int K, int C)
{
    __shared__ float tile[32][33];
    int c0 = blockIdx.x * 32, k0 = blockIdx.y * 32;
    int x = threadIdx.x, y = threadIdx.y;
#pragma unroll
    for (int i = 0; i < 32; i += 8)
        tile[y + i][x] = src[(size_t)(k0 + y + i) * C + c0 + x];
    __syncthreads();
#pragma unroll
    for (int i = 0; i < 32; i += 8) {
        float v = tile[x][y + i];
        __nv_bfloat16 h, l;
        split1(v, h, l);
        size_t off = (size_t)(c0 + y + i) * K + k0 + x;
        dh[off] = h; dl[off] = l;
    }
}

// ---------------------------------------------------------------------------
// bf16x3 tensor-core GEMM:  C[M,N] = A[M,1024] @ B[N,1024]^T   (pre-split bf16)
// CTA 128x128, BK=32, 8 warps (2x4), warp tile 64x32 via m16n8k16.
// cp.async double buffer, ldmatrix frags; A frags loaded per-mi to keep the
// live register set under the 128-reg cap (2 CTAs/SM, no spills).
// ---------------------------------------------------------------------------
#define LSTRIDE   40                              // bf16 elems per smem row (80B)
#define ARR_ELEMS (128 * LSTRIDE)                 // 5120
#define STAGE_ELEMS (4 * ARR_ELEMS)
#define SMEM_GEMM (2 * STAGE_ELEMS * 2)           // 81920 bytes

template <int NSTRIDE, bool TRIM>
__global__ __launch_bounds__(256, 2)
void gemm_bf16x3_kernel(const __nv_bfloat16* __restrict__ Ahg,
                        const __nv_bfloat16* __restrict__ Alg,
                        const __nv_bfloat16* __restrict__ Bhg,
                        const __nv_bfloat16* __restrict__ Blg,
                        float* __restrict__ C)
{
    extern __shared__ __nv_bfloat16 sm[];
    const int tid  = threadIdx.x;
    const int bn   = blockIdx.x;
    const int bm   = blockIdx.y;
    const int warp = tid >> 5;
    const int lane = tid & 31;
    const int wm   = warp >> 2;
    const int wn   = warp & 3;
    const int g    = lane >> 2;
    const int t4   = lane & 3;

    float acc[4][4][4];
#pragma unroll
    for (int mi = 0; mi < 4; mi++)
#pragma unroll
        for (int ni = 0; ni < 4; ni++)
#pragma unroll
            for (int r = 0; r < 4; r++) acc[mi][ni][r] = 0.f;

    // cp.async source row pointers / smem slot, hoisted
    const int ld_row = tid >> 1;                 // 0..127 (2 threads per row)
    const int ld_seg = (tid & 1) * 2;            // segment pair: 0 or 2
    const __nv_bfloat16* srcA[2] = { Ahg + ((size_t)bm * 128 + ld_row) * KTOT,
                                     Alg + ((size_t)bm * 128 + ld_row) * KTOT };
    const __nv_bfloat16* srcB[2] = { Bhg + ((size_t)bn * 128 + ld_row) * KTOT,
                                     Blg + ((size_t)bn * 128 + ld_row) * KTOT };
    const uint32_t sm_row = smem_u32(sm) + (ld_row * LSTRIDE + ld_seg * 8) * 2;

    auto issue = [&](int kc) {
        const int buf = kc & 1;
        const int k0  = kc * BK;
        uint32_t dst = sm_row + buf * (STAGE_ELEMS * 2);
#pragma unroll
        for (int arr = 0; arr < 2; arr++) {
            cp_async16(dst + (arr * ARR_ELEMS) * 2,       srcA[arr] + k0 + ld_seg * 8);
            cp_async16(dst + (arr * ARR_ELEMS) * 2 + 16,  srcA[arr] + k0 + ld_seg * 8 + 8);
            cp_async16(dst + ((2 + arr) * ARR_ELEMS) * 2,      srcB[arr] + k0 + ld_seg * 8);
            cp_async16(dst + ((2 + arr) * ARR_ELEMS) * 2 + 16, srcB[arr] + k0 + ld_seg * 8 + 8);
        }
        CP_COMMIT();
    };

    issue(0);

    const uint32_t smem0 = smem_u32(sm);
    // fragment base addresses (byte offsets within one array)
    const int a_row_off = (wm * 64 + (lane & 15)) * 80 + (lane >> 4) * 16;
    const int b_row_off = (wn * 32 + ((lane >> 4) << 3) + (lane & 7)) * 80
                        + ((lane >> 3) & 1) * 16;

    for (int kc = 0; kc < NCHUNK; kc++) {
        const int buf = kc & 1;
        if (kc + 1 < NCHUNK) { issue(kc + 1); CP_WAIT(1); }
        else                 { CP_WAIT(0); }
        __syncthreads();

        const uint32_t base = smem0 + buf * (STAGE_ELEMS * 2);
        const uint32_t aAh = base;
        const uint32_t aAl = base + ARR_ELEMS * 2;
        const uint32_t aBh = base + 2 * ARR_ELEMS * 2;
        const uint32_t aBl = base + 3 * ARR_ELEMS * 2;

#pragma unroll
        for (int ks = 0; ks < 2; ks++) {
            const int kb = ks * 32;   // byte offset of k16 step
            uint32_t bh[2][4], bl[2][4];
#pragma unroll
            for (int nip = 0; nip < 2; nip++) {
                ldsm_x4(bh[nip], aBh + b_row_off + nip * (16 * 80) + kb);
                ldsm_x4(bl[nip], aBl + b_row_off + nip * (16 * 80) + kb);
            }
#pragma unroll
            for (int mi = 0; mi < 4; mi++) {
                uint32_t ah[4], al[4];
                ldsm_x4(ah, aAh + a_row_off + mi * (16 * 80) + kb);
                ldsm_x4(al, aAl + a_row_off + mi * (16 * 80) + kb);
#pragma unroll
                for (int nip = 0; nip < 2; nip++) {
#pragma unroll
                    for (int s = 0; s < 2; s++) {
                        int ni = nip * 2 + s;
                        uint32_t b0h = bh[nip][2*s], b1h = bh[nip][2*s+1];
                        uint32_t b0l = bl[nip][2*s], b1l = bl[nip][2*s+1];
                        mma16816(acc[mi][ni], ah[0],ah[1],ah[2],ah[3], b0h,b1h);
                        mma16816(acc[mi][ni], ah[0],ah[1],ah[2],ah[3], b0l,b1l);
                        mma16816(acc[mi][ni], al[0],al[1],al[2],al[3], b0h,b1h);
                    }
                }
            }
        }
        __syncthreads();
    }

    // ---- epilogue ----
#pragma unroll
    for (int mi = 0; mi < 4; mi++) {
#pragma unroll
        for (int half = 0; half < 2; half++) {
            int m = bm * 128 + wm * 64 + mi * 16 + g + half * 8;
            float* dst = nullptr;
            if (TRIM) {
                int b = m / NP, t = m - b * NP;
                if (t < NSEQ) dst = &C[((size_t)(b * NSEQ + t)) * NSTRIDE];
            } else {
                dst = &C[(size_t)m * NSTRIDE];
            }
            if (dst) {
                int ncol = bn * 128 + wn * 32 + t4 * 2;
#pragma unroll
                for (int ni = 0; ni < 4; ni++) {
                    float2 v = make_float2(acc[mi][ni][half * 2], acc[mi][ni][half * 2 + 1]);
                    *(float2*)&dst[ncol + ni * 8] = v;
                }
            }
        }
    }
}

// ---------------------------------------------------------------------------
// Text attention: per (b,h), 128 queries x 128 keys, causal. fp32.
// ---------------------------------------------------------------------------
__global__ __launch_bounds__(128) void text_attn_kernel()
{
    extern __shared__ float smf[];
    float* KV = smf;
    float* S  = smf + 128 * 64;

    const int bh = blockIdx.x;
    const int b  = bh / NHEAD;
    const int h  = bh - b * NHEAD;
    const int i  = threadIdx.x;

    for (int idx = threadIdx.x; idx < 128 * 64 / 4; idx += 128) {
        int t = idx >> 4, c4 = idx & 15;
        *(float4*)&KV[t * 64 + c4 * 4] =
            *(const float4*)&g_qkv[((size_t)(b * NP + t)) * TRIPLE + DIMC + h * DHEAD + c4 * 4];
    }
    __syncthreads();

    float q[64];
    {
        const float* qp = &g_qkv[((size_t)(b * NP + i)) * TRIPLE + h * DHEAD];
#pragma unroll
        for (int d = 0; d < 64; d++) q[d] = qp[d] * 0.125f;
    }

    float mx = -FLT_MAX;
    for (int j = 0; j <= i; j++) {
        const float* kp = &KV[j * 64];
        float s0 = 0.f, s1 = 0.f, s2 = 0.f, s3 = 0.f;
#pragma unroll
        for (int d = 0; d < 64; d += 4) {
            s0 += q[d+0] * kp[d+0]; s1 += q[d+1] * kp[d+1];
            s2 += q[d+2] * kp[d+2]; s3 += q[d+3] * kp[d+3];
        }
        float s = (s0 + s1) + (s2 + s3);
        S[i * 128 + j] = s;
        mx = fmaxf(mx, s);
    }
    float sum = 0.f;
    for (int j = 0; j <= i; j++) {
        float p = __expf(S[i * 128 + j] - mx);
        S[i * 128 + j] = p;
        sum += p;
    }
    __syncthreads();

    for (int idx = threadIdx.x; idx < 128 * 64 / 4; idx += 128) {
        int t = idx >> 4, c4 = idx & 15;
        *(float4*)&KV[t * 64 + c4 * 4] =
            *(const float4*)&g_qkv[((size_t)(b * NP + t)) * TRIPLE + 2 * DIMC + h * DHEAD + c4 * 4];
    }
    __syncthreads();

    float o[64];
#pragma unroll
    for (int d = 0; d < 64; d++) o[d] = 0.f;
    for (int j = 0; j <= i; j++) {
        float p = S[i * 128 + j];
        const float* vp = &KV[j * 64];
#pragma unroll
        for (int d = 0; d < 64; d++) o[d] += p * vp[d];
    }
    float inv = 1.f / sum;
    float* op = &g_attn[((size_t)(b * NP + i)) * DIMC + h * DHEAD];
#pragma unroll
    for (int d = 0; d < 64; d++) op[d] = o[d] * inv;
}

// ---------------------------------------------------------------------------
// Image (axial) attention — fp16 smem (48KB/block -> 4 blocks/SM).
// ---------------------------------------------------------------------------
#define SMEM_IMG ((192 * 64 + 64 * 192) * 2)   // 49152 bytes

__global__ __launch_bounds__(64) void img_attn_kernel()
{
    extern __shared__ __half smh[];
    __half* KV = smh;                 // 192 x 64 fp16
    __half* S  = smh + 192 * 64;      // 64 x 192 fp16
    __shared__ uint8_t smask[TEXTL];

    const int bid = blockIdx.x;
    const int xr  = bid & 63;
    const int h   = (bid >> 6) & 15;
    const int b   = bid >> 10;
    const int i   = threadIdx.x;

    for (int j = threadIdx.x; j < TEXTL; j += 64) smask[j] = g_mask[b * TEXTL + j];

    for (int idx = threadIdx.x; idx < 192 * 16; idx += 64) {
        int r = idx >> 4, c4 = idx & 15;
        int t = (r < TEXTL) ? r : (TEXTL + xr * 64 + (r - TEXTL));
        float4 v = *(const float4*)&g_qkv[((size_t)(b * NP + t)) * TRIPLE + DIMC + h * DHEAD + c4 * 4];
        __half2* dst = (__half2*)&KV[r * 64 + c4 * 4];
        dst[0] = __floats2half2_rn(v.x, v.y);
        dst[1] = __floats2half2_rn(v.z, v.w);
    }
    __syncthreads();

    float q[64];
    {
        const int tq = TEXTL + xr * 64 + i;
        const float* qp = &g_qkv[((size_t)(b * NP + tq)) * TRIPLE + h * DHEAD];
#pragma unroll
        for (int d = 0; d < 64; d++) q[d] = qp[d] * 0.125f;
    }

    auto dot192 = [&](int r) -> float {
        const uint4* kp = (const uint4*)&KV[r * 64];
        float s0 = 0.f, s1 = 0.f, s2 = 0.f, s3 = 0.f;
#pragma unroll
        for (int w = 0; w < 8; w++) {
            uint4 u = kp[w];
            float2 f0 = __half22float2(*(__half2*)&u.x);
            float2 f1 = __half22float2(*(__half2*)&u.y);
            float2 f2 = __half22float2(*(__half2*)&u.z);
            float2 f3 = __half22float2(*(__half2*)&u.w);
            int d = w * 8;
            s0 += q[d+0] * f0.x; s1 += q[d+1] * f0.y;
            s2 += q[d+2] * f1.x; s3 += q[d+3] * f1.y;
            s0 += q[d+4] * f2.x; s1 += q[d+5] * f2.y;
            s2 += q[d+6] * f3.x; s3 += q[d+7] * f3.y;
        }
        return (s0 + s1) + (s2 + s3);
    };

    float mx = -FLT_MAX;
    for (int j = 0; j < TEXTL; j++) {
        float s = smask[j] ? dot192(j) : -65000.f;
        S[i * 192 + j] = __float2half_rn(s);
        mx = fmaxf(mx, s);
    }
    for (int j = 0; j <= i; j++) {
        float s = dot192(TEXTL + j);
        S[i * 192 + TEXTL + j] = __float2half_rn(s);
        mx = fmaxf(mx, s);
    }

    float sum = 0.f;
    for (int j = 0; j < TEXTL; j++) {
        float s = __half2float(S[i * 192 + j]);
        float p = (s < -60000.f) ? 0.f : __expf(s - mx);
        S[i * 192 + j] = __float2half_rn(p);
        sum += p;
    }
    for (int j = 0; j <= i; j++) {
        float p = __expf(__half2float(S[i * 192 + TEXTL + j]) - mx);
        S[i * 192 + TEXTL + j] = __float2half_rn(p);
        sum += p;
    }
    __syncthreads();

    for (int idx = threadIdx.x; idx < 192 * 16; idx += 64) {
        int r = idx >> 4, c4 = idx & 15;
        int t = (r < TEXTL) ? r : (TEXTL + xr * 64 + (r - TEXTL));
        float4 v = *(const float4*)&g_qkv[((size_t)(b * NP + t)) * TRIPLE + 2 * DIMC + h * DHEAD + c4 * 4];
        __half2* dst = (__half2*)&KV[r * 64 + c4 * 4];
        dst[0] = __floats2half2_rn(v.x, v.y);
        dst[1] = __floats2half2_rn(v.z, v.w);
    }
    __syncthreads();

    float o[64];
#pragma unroll
    for (int d = 0; d < 64; d++) o[d] = 0.f;

    auto accum = [&](int r, float p) {
        const uint4* vp = (const uint4*)&KV[r * 64];
#pragma unroll
        for (int w = 0; w < 8; w++) {
            uint4 u = vp[w];
            float2 f0 = __half22float2(*(__half2*)&u.x);
            float2 f1 = __half22float2(*(__half2*)&u.y);
            float2 f2 = __half22float2(*(__half2*)&u.z);
            float2 f3 = __half22float2(*(__half2*)&u.w);
            int d = w * 8;
            o[d+0] += p * f0.x; o[d+1] += p * f0.y;
            o[d+2] += p * f1.x; o[d+3] += p * f1.y;
            o[d+4] += p * f2.x; o[d+5] += p * f2.y;
            o[d+6] += p * f3.x; o[d+7] += p * f3.y;
        }
    };

    for (int j = 0; j < TEXTL; j++)
        accum(j, __half2float(S[i * 192 + j]));
    for (int j = 0; j <= i; j++)
        accum(TEXTL + j, __half2float(S[i * 192 + TEXTL + j]));

    float inv = 1.f / sum;
    const int tq = TEXTL + xr * 64 + i;
    float* op = &g_attn[((size_t)(b * NP + tq)) * DIMC + h * DHEAD];
#pragma unroll
    for (int d = 0; d < 64; d++) op[d] = o[d] * inv;
}

// ---------------------------------------------------------------------------
// Launch
// ---------------------------------------------------------------------------
extern "C" void kernel_launch(void* const* d_in, const int* in_sizes, int n_in,
                              void* d_out, int out_size)
{
    const float* x     = nullptr;
    const void*  mask  = nullptr;
    const float* w_qkv = nullptr;
    const float* w_out = nullptr;
    for (int i = 0; i < n_in; i++) {
        long long sz = in_sizes[i];
        if      (sz == (long long)BATCH * NSEQ * DIMC) x     = (const float*)d_in[i];
        else if (sz == BATCH * TEXTL)                  mask  = d_in[i];
        else if (sz == (long long)DIMC * TRIPLE)       w_qkv = (const float*)d_in[i];
        else if (sz == (long long)DIMC * DIMC)         w_out = (const float*)d_in[i];
    }
    float* out = (float*)d_out;

    __nv_bfloat16 *ah, *al, *bhq, *blq, *bho, *blo;
    float *attn, *qkv;
    cudaGetSymbolAddress((void**)&ah,  g_ah);
    cudaGetSymbolAddress((void**)&al,  g_al);
    cudaGetSymbolAddress((void**)&bhq, g_bh_qkv);
    cudaGetSymbolAddress((void**)&blq, g_bl_qkv);
    cudaGetSymbolAddress((void**)&bho, g_bh_out);
    cudaGetSymbolAddress((void**)&blo, g_bl_out);
    cudaGetSymbolAddress((void**)&attn, g_attn);
    cudaGetSymbolAddress((void**)&qkv,  g_qkv);

    const int SMEM_TXT = 98304;
    cudaFuncSetAttribute(text_attn_kernel, cudaFuncAttributeMaxDynamicSharedMemorySize, SMEM_TXT);
    cudaFuncSetAttribute(img_attn_kernel,  cudaFuncAttributeMaxDynamicSharedMemorySize, SMEM_IMG);
    cudaFuncSetAttribute(gemm_bf16x3_kernel<TRIPLE, false>,
                         cudaFuncAttributeMaxDynamicSharedMemorySize, SMEM_GEMM);
    cudaFuncSetAttribute(gemm_bf16x3_kernel<DIMC, true>,
                         cudaFuncAttributeMaxDynamicSharedMemorySize, SMEM_GEMM);

    normalize_mask_kernel<<<1, 256>>>(mask);
    split_w_kernel<<<dim3(TRIPLE / 32, KTOT / 32), dim3(32, 8)>>>(w_qkv, bhq, blq, KTOT, TRIPLE);
    split_w_kernel<<<dim3(DIMC / 32,   KTOT / 32), dim3(32, 8)>>>(w_out, bho, blo, KTOT, DIMC);
    split_a_kernel<true><<<MROWS, 256>>>(x);

    dim3 g1(TRIPLE / 128, MROWS / 128);  // 24 x 264
    gemm_bf16x3_kernel<TRIPLE, false><<<g1, 256, SMEM_GEMM>>>(ah, al, bhq, blq, qkv);

    text_attn_kernel<<<BATCH * NHEAD, 128, SMEM_TXT>>>();
    img_attn_kernel<<<BATCH * NHEAD * IMGDIM, 64, SMEM_IMG>>>();

    split_a_kernel<false><<<MROWS, 256>>>(attn);

    dim3 g2(DIMC / 128, MROWS / 128);    // 8 x 264
    gemm_bf16x3_kernel<DIMC, true><<<g2, 256, SMEM_GEMM>>>(ah, al, bho, blo, out);
}

// round 7
// speedup vs baseline: 1.8984x; 1.2028x over previous
#include <cuda_runtime.h>
#include <cuda_fp16.h>
#include <float.h>
#include <stdint.h>

// ---------------------------------------------------------------------------
// Problem constants
// ---------------------------------------------------------------------------
#define BATCH   8
#define NP      4224
#define NSEQ    4223
#define TEXTL   128
#define IMGDIM  64
#define NHEAD   16
#define DHEAD   64
#define DIMC    1024
#define TRIPLE  3072
#define MROWS   (BATCH*NP)    // 33792
#define KTOT    1024
#define BK      32
#define NCHUNK  (KTOT / BK)

// Scratch (device globals — no allocation allowed)
__device__ float   g_qkv  [(size_t)BATCH * NP * TRIPLE];
__device__ __half  g_ah   [(size_t)MROWS * KTOT];     // A hi (x, then attn out)
__device__ __half  g_al   [(size_t)MROWS * KTOT];     // A lo
__device__ __half  g_b_qkv[(size_t)TRIPLE * KTOT];    // w_qkv^T fp16
__device__ __half  g_b_out[(size_t)DIMC * KTOT];      // w_out^T fp16
__device__ uint8_t g_mask [BATCH * TEXTL];

// ---------------------------------------------------------------------------
// PTX helpers (baseline PTX only — compute_103 virtual arch)
// ---------------------------------------------------------------------------
__device__ __forceinline__ uint32_t smem_u32(const void* p) {
    uint32_t a;
    asm("{ .reg .u64 t; cvta.to.shared.u64 t, %1; cvt.u32.u64 %0, t; }" : "=r"(a) : "l"(p));
    return a;
}
__device__ __forceinline__ void mma16816(float d[4],
    uint32_t a0, uint32_t a1, uint32_t a2, uint32_t a3, uint32_t b0, uint32_t b1)
{
    asm volatile(
        "mma.sync.aligned.m16n8k16.row.col.f32.f16.f16.f32 "
        "{%0,%1,%2,%3},{%4,%5,%6,%7},{%8,%9},{%0,%1,%2,%3};\n"
        : "+f"(d[0]), "+f"(d[1]), "+f"(d[2]), "+f"(d[3])
        : "r"(a0), "r"(a1), "r"(a2), "r"(a3), "r"(b0), "r"(b1));
}
__device__ __forceinline__ void ldsm_x4(uint32_t r[4], uint32_t addr)
{
    asm volatile("ldmatrix.sync.aligned.m8n8.x4.shared.b16 {%0,%1,%2,%3}, [%4];"
                 : "=r"(r[0]), "=r"(r[1]), "=r"(r[2]), "=r"(r[3]) : "r"(addr));
}
__device__ __forceinline__ void cp_async16(uint32_t dst, const void* src)
{
    asm volatile("cp.async.cg.shared.global [%0], [%1], 16;" :: "r"(dst), "l"(src) : "memory");
}
#define CP_COMMIT()  asm volatile("cp.async.commit_group;" ::: "memory")
#define CP_WAIT(N)   asm volatile("cp.async.wait_group %0;" :: "n"(N) : "memory")

// ---------------------------------------------------------------------------
// Mask normalization (bool mask may arrive as int32 / float32 / uint8)
// ---------------------------------------------------------------------------
__global__ void normalize_mask_kernel(const void* __restrict__ mask_raw)
{
    __shared__ int cls;
    const uint32_t* w = (const uint32_t*)mask_raw;
    const uint8_t*  c = (const uint8_t*)mask_raw;
    if (threadIdx.x == 0) {
        bool all_int = true, all_f32 = true;
        for (int i = 0; i < 256; i++) {
            uint32_t v = w[i];
            if (v != 0u && v != 1u)          all_int = false;
            if (v != 0u && v != 0x3F800000u) all_f32 = false;
        }
        cls = (all_int || all_f32) ? 0 : 1;
    }
    __syncthreads();
    for (int i = threadIdx.x; i < BATCH * TEXTL; i += blockDim.x)
        g_mask[i] = (cls == 0) ? (w[i] != 0u) : (c[i] != 0u);
}

// ---------------------------------------------------------------------------
// fp32 -> (hi, lo) fp16 split
// ---------------------------------------------------------------------------
__device__ __forceinline__ void split1h(float v, __half& h, __half& l)
{
    h = __float2half_rn(v);
    l = __float2half_rn(v - __half2float(h));
}

// A-side split of x (with batch padding): g_ah/g_al [MROWS][KTOT]
__global__ __launch_bounds__(256) void split_a_kernel(const float* __restrict__ src)
{
    int idx = blockIdx.x * 256 + threadIdx.x;     // one float4 per thread
    int m   = idx >> 8;
    int c4  = idx & 255;
    float4 v = make_float4(0.f, 0.f, 0.f, 0.f);
    {
        int b = m / NP, t = m - b * NP;
        if (t < NSEQ) v = *(const float4*)&src[((size_t)(b * NSEQ + t)) * KTOT + c4 * 4];
    }
    __half h[4], l[4];
    split1h(v.x, h[0], l[0]); split1h(v.y, h[1], l[1]);
    split1h(v.z, h[2], l[2]); split1h(v.w, h[3], l[3]);
    size_t off = (size_t)m * KTOT + c4 * 4;
    *(uint2*)&g_ah[off] = *(uint2*)h;
    *(uint2*)&g_al[off] = *(uint2*)l;
}

// W-side: transpose + single-round fp16.  src [K][C] fp32 -> dst [C][K] fp16
__global__ __launch_bounds__(256) void conv_w_kernel(
    const float* __restrict__ src, __half* __restrict__ dst, int K, int C)
{
    __shared__ float tile[32][33];
    int c0 = blockIdx.x * 32, k0 = blockIdx.y * 32;
    int x = threadIdx.x, y = threadIdx.y;
#pragma unroll
    for (int i = 0; i < 32; i += 8)
        tile[y + i][x] = src[(size_t)(k0 + y + i) * C + c0 + x];
    __syncthreads();
#pragma unroll
    for (int i = 0; i < 32; i += 8)
        dst[(size_t)(c0 + y + i) * K + k0 + x] = __float2half_rn(tile[x][y + i]);
}

// ---------------------------------------------------------------------------
// fp16x2 tensor-core GEMM:  C[M,N] = (Ah+Al)[M,1024] @ B[N,1024]^T
// CTA 128x128, BK=32, 8 warps (2x4), warp tile 64x32, m16n8k16.
// cp.async double buffer, ldmatrix; 2 MMA products per acc (Ah*B + Al*B).
// ---------------------------------------------------------------------------
#define LSTRIDE   40                              // fp16 elems per smem row (80B)
#define ARR_ELEMS (128 * LSTRIDE)                 // 5120
#define STAGE_ELEMS (3 * ARR_ELEMS)               // Ah, Al, B
#define SMEM_GEMM (2 * STAGE_ELEMS * 2)           // 61440 bytes

template <int NSTRIDE, bool TRIM>
__global__ __launch_bounds__(256, 2)
void gemm_fp16x2_kernel(const __half* __restrict__ Ahg,
                        const __half* __restrict__ Alg,
                        const __half* __restrict__ Bg,
                        float* __restrict__ C)
{
    extern __shared__ __half sm[];
    const int tid  = threadIdx.x;
    const int bn   = blockIdx.x;
    const int bm   = blockIdx.y;
    const int warp = tid >> 5;
    const int lane = tid & 31;
    const int wm   = warp >> 2;
    const int wn   = warp & 3;
    const int g    = lane >> 2;
    const int t4   = lane & 3;

    float acc[4][4][4];
#pragma unroll
    for (int mi = 0; mi < 4; mi++)
#pragma unroll
        for (int ni = 0; ni < 4; ni++)
#pragma unroll
            for (int r = 0; r < 4; r++) acc[mi][ni][r] = 0.f;

    // loader: 2 threads per row, each covers 32B of the 64B row (per array)
    const int ld_row = tid >> 1;
    const int ld_seg = (tid & 1) * 2;
    const __half* srcAh = Ahg + ((size_t)bm * 128 + ld_row) * KTOT + ld_seg * 8;
    const __half* srcAl = Alg + ((size_t)bm * 128 + ld_row) * KTOT + ld_seg * 8;
    const __half* srcB  = Bg  + ((size_t)bn * 128 + ld_row) * KTOT + ld_seg * 8;
    const uint32_t sm_row = smem_u32(sm) + (ld_row * LSTRIDE + ld_seg * 8) * 2;

    auto issue = [&](int kc) {
        const int buf = kc & 1;
        const int k0  = kc * BK;
        uint32_t dst = sm_row + buf * (STAGE_ELEMS * 2);
        cp_async16(dst,                          srcAh + k0);
        cp_async16(dst + 16,                     srcAh + k0 + 8);
        cp_async16(dst + ARR_ELEMS * 2,          srcAl + k0);
        cp_async16(dst + ARR_ELEMS * 2 + 16,     srcAl + k0 + 8);
        cp_async16(dst + 2 * ARR_ELEMS * 2,      srcB  + k0);
        cp_async16(dst + 2 * ARR_ELEMS * 2 + 16, srcB  + k0 + 8);
        CP_COMMIT();
    };

    issue(0);

    const uint32_t smem0 = smem_u32(sm);
    const int a_row_off = (wm * 64 + (lane & 15)) * 80 + (lane >> 4) * 16;
    const int b_row_off = (wn * 32 + ((lane >> 4) << 3) + (lane & 7)) * 80
                        + ((lane >> 3) & 1) * 16;

    for (int kc = 0; kc < NCHUNK; kc++) {
        const int buf = kc & 1;
        if (kc + 1 < NCHUNK) { issue(kc + 1); CP_WAIT(1); }
        else                 { CP_WAIT(0); }
        __syncthreads();

        const uint32_t base = smem0 + buf * (STAGE_ELEMS * 2);
        const uint32_t aAh = base;
        const uint32_t aAl = base + ARR_ELEMS * 2;
        const uint32_t aB  = base + 2 * ARR_ELEMS * 2;

#pragma unroll
        for (int ks = 0; ks < 2; ks++) {
            const int kb = ks * 32;
            uint32_t bf[2][4];
#pragma unroll
            for (int nip = 0; nip < 2; nip++)
                ldsm_x4(bf[nip], aB + b_row_off + nip * (16 * 80) + kb);
#pragma unroll
            for (int mi = 0; mi < 4; mi++) {
                uint32_t ah[4], al[4];
                ldsm_x4(ah, aAh + a_row_off + mi * (16 * 80) + kb);
                ldsm_x4(al, aAl + a_row_off + mi * (16 * 80) + kb);
#pragma unroll
                for (int nip = 0; nip < 2; nip++) {
#pragma unroll
                    for (int s = 0; s < 2; s++) {
                        int ni = nip * 2 + s;
                        uint32_t b0 = bf[nip][2*s], b1 = bf[nip][2*s+1];
                        mma16816(acc[mi][ni], ah[0],ah[1],ah[2],ah[3], b0,b1);
                        mma16816(acc[mi][ni], al[0],al[1],al[2],al[3], b0,b1);
                    }
                }
            }
        }
        __syncthreads();
    }

    // ---- epilogue ----
#pragma unroll
    for (int mi = 0; mi < 4; mi++) {
#pragma unroll
        for (int half = 0; half < 2; half++) {
            int m = bm * 128 + wm * 64 + mi * 16 + g + half * 8;
            float* dst = nullptr;
            if (TRIM) {
                int b = m / NP, t = m - b * NP;
                if (t < NSEQ) dst = &C[((size_t)(b * NSEQ + t)) * NSTRIDE];
            } else {
                dst = &C[(size_t)m * NSTRIDE];
            }
            if (dst) {
                int ncol = bn * 128 + wn * 32 + t4 * 2;
#pragma unroll
                for (int ni = 0; ni < 4; ni++) {
                    float2 v = make_float2(acc[mi][ni][half * 2], acc[mi][ni][half * 2 + 1]);
                    *(float2*)&dst[ncol + ni * 8] = v;
                }
            }
        }
    }
}

// ---------------------------------------------------------------------------
// Attention epilogue helper: write o*inv as fp16 hi/lo into g_ah/g_al
// ---------------------------------------------------------------------------
__device__ __forceinline__ void store_attn_row(
    const float* o, float inv, size_t row, int h)
{
    size_t off = row * KTOT + h * DHEAD;
#pragma unroll
    for (int d = 0; d < 64; d += 2) {
        float v0 = o[d] * inv, v1 = o[d + 1] * inv;
        __half h0, l0, h1, l1;
        split1h(v0, h0, l0);
        split1h(v1, h1, l1);
        *(__half2*)&g_ah[off + d] = __halves2half2(h0, h1);
        *(__half2*)&g_al[off + d] = __halves2half2(l0, l1);
    }
}

// ---------------------------------------------------------------------------
// Text attention: per (b,h), 128 queries x 128 keys, causal. fp32.
// ---------------------------------------------------------------------------
__global__ __launch_bounds__(128) void text_attn_kernel()
{
    extern __shared__ float smf[];
    float* KV = smf;
    float* S  = smf + 128 * 64;

    const int bh = blockIdx.x;
    const int b  = bh / NHEAD;
    const int h  = bh - b * NHEAD;
    const int i  = threadIdx.x;

    for (int idx = threadIdx.x; idx < 128 * 64 / 4; idx += 128) {
        int t = idx >> 4, c4 = idx & 15;
        *(float4*)&KV[t * 64 + c4 * 4] =
            *(const float4*)&g_qkv[((size_t)(b * NP + t)) * TRIPLE + DIMC + h * DHEAD + c4 * 4];
    }
    __syncthreads();

    float q[64];
    {
        const float* qp = &g_qkv[((size_t)(b * NP + i)) * TRIPLE + h * DHEAD];
#pragma unroll
        for (int d = 0; d < 64; d++) q[d] = qp[d] * 0.125f;
    }

    float mx = -FLT_MAX;
    for (int j = 0; j <= i; j++) {
        const float* kp = &KV[j * 64];
        float s0 = 0.f, s1 = 0.f, s2 = 0.f, s3 = 0.f;
#pragma unroll
        for (int d = 0; d < 64; d += 4) {
            s0 += q[d+0] * kp[d+0]; s1 += q[d+1] * kp[d+1];
            s2 += q[d+2] * kp[d+2]; s3 += q[d+3] * kp[d+3];
        }
        float s = (s0 + s1) + (s2 + s3);
        S[i * 128 + j] = s;
        mx = fmaxf(mx, s);
    }
    float sum = 0.f;
    for (int j = 0; j <= i; j++) {
        float p = __expf(S[i * 128 + j] - mx);
        S[i * 128 + j] = p;
        sum += p;
    }
    __syncthreads();

    for (int idx = threadIdx.x; idx < 128 * 64 / 4; idx += 128) {
        int t = idx >> 4, c4 = idx & 15;
        *(float4*)&KV[t * 64 + c4 * 4] =
            *(const float4*)&g_qkv[((size_t)(b * NP + t)) * TRIPLE + 2 * DIMC + h * DHEAD + c4 * 4];
    }
    __syncthreads();

    float o[64];
#pragma unroll
    for (int d = 0; d < 64; d++) o[d] = 0.f;
    for (int j = 0; j <= i; j++) {
        float p = S[i * 128 + j];
        const float* vp = &KV[j * 64];
#pragma unroll
        for (int d = 0; d < 64; d++) o[d] += p * vp[d];
    }
    store_attn_row(o, 1.f / sum, (size_t)(b * NP + i), h);
}

// ---------------------------------------------------------------------------
// Image (axial) attention — fp16 smem (48KB/block).
// ---------------------------------------------------------------------------
#define SMEM_IMG ((192 * 64 + 64 * 192) * 2)   // 49152 bytes

__global__ __launch_bounds__(64) void img_attn_kernel()
{
    extern __shared__ __half smh[];
    __half* KV = smh;                 // 192 x 64 fp16
    __half* S  = smh + 192 * 64;      // 64 x 192 fp16
    __shared__ uint8_t smask[TEXTL];

    const int bid = blockIdx.x;
    const int xr  = bid & 63;
    const int h   = (bid >> 6) & 15;
    const int b   = bid >> 10;
    const int i   = threadIdx.x;

    for (int j = threadIdx.x; j < TEXTL; j += 64) smask[j] = g_mask[b * TEXTL + j];

    for (int idx = threadIdx.x; idx < 192 * 16; idx += 64) {
        int r = idx >> 4, c4 = idx & 15;
        int t = (r < TEXTL) ? r : (TEXTL + xr * 64 + (r - TEXTL));
        float4 v = *(const float4*)&g_qkv[((size_t)(b * NP + t)) * TRIPLE + DIMC + h * DHEAD + c4 * 4];
        __half2* dst = (__half2*)&KV[r * 64 + c4 * 4];
        dst[0] = __floats2half2_rn(v.x, v.y);
        dst[1] = __floats2half2_rn(v.z, v.w);
    }
    __syncthreads();

    float q[64];
    {
        const int tq = TEXTL + xr * 64 + i;
        const float* qp = &g_qkv[((size_t)(b * NP + tq)) * TRIPLE + h * DHEAD];
#pragma unroll
        for (int d = 0; d < 64; d++) q[d] = qp[d] * 0.125f;
    }

    auto dot192 = [&](int r) -> float {
        const uint4* kp = (const uint4*)&KV[r * 64];
        float s0 = 0.f, s1 = 0.f, s2 = 0.f, s3 = 0.f;
#pragma unroll
        for (int w = 0; w < 8; w++) {
            uint4 u = kp[w];
            float2 f0 = __half22float2(*(__half2*)&u.x);
            float2 f1 = __half22float2(*(__half2*)&u.y);
            float2 f2 = __half22float2(*(__half2*)&u.z);
            float2 f3 = __half22float2(*(__half2*)&u.w);
            int d = w * 8;
            s0 += q[d+0] * f0.x; s1 += q[d+1] * f0.y;
            s2 += q[d+2] * f1.x; s3 += q[d+3] * f1.y;
            s0 += q[d+4] * f2.x; s1 += q[d+5] * f2.y;
            s2 += q[d+6] * f3.x; s3 += q[d+7] * f3.y;
        }
        return (s0 + s1) + (s2 + s3);
    };

    float mx = -FLT_MAX;
    for (int j = 0; j < TEXTL; j++) {
        float s = smask[j] ? dot192(j) : -65000.f;
        S[i * 192 + j] = __float2half_rn(s);
        mx = fmaxf(mx, s);
    }
    for (int j = 0; j <= i; j++) {
        float s = dot192(TEXTL + j);
        S[i * 192 + TEXTL + j] = __float2half_rn(s);
        mx = fmaxf(mx, s);
    }

    float sum = 0.f;
    for (int j = 0; j < TEXTL; j++) {
        float s = __half2float(S[i * 192 + j]);
        float p = (s < -60000.f) ? 0.f : __expf(s - mx);
        S[i * 192 + j] = __float2half_rn(p);
        sum += p;
    }
    for (int j = 0; j <= i; j++) {
        float p = __expf(__half2float(S[i * 192 + TEXTL + j]) - mx);
        S[i * 192 + TEXTL + j] = __float2half_rn(p);
        sum += p;
    }
    __syncthreads();

    for (int idx = threadIdx.x; idx < 192 * 16; idx += 64) {
        int r = idx >> 4, c4 = idx & 15;
        int t = (r < TEXTL) ? r : (TEXTL + xr * 64 + (r - TEXTL));
        float4 v = *(const float4*)&g_qkv[((size_t)(b * NP + t)) * TRIPLE + 2 * DIMC + h * DHEAD + c4 * 4];
        __half2* dst = (__half2*)&KV[r * 64 + c4 * 4];
        dst[0] = __floats2half2_rn(v.x, v.y);
        dst[1] = __floats2half2_rn(v.z, v.w);
    }
    __syncthreads();

    float o[64];
#pragma unroll
    for (int d = 0; d < 64; d++) o[d] = 0.f;

    auto accum = [&](int r, float p) {
        const uint4* vp = (const uint4*)&KV[r * 64];
#pragma unroll
        for (int w = 0; w < 8; w++) {
            uint4 u = vp[w];
            float2 f0 = __half22float2(*(__half2*)&u.x);
            float2 f1 = __half22float2(*(__half2*)&u.y);
            float2 f2 = __half22float2(*(__half2*)&u.z);
            float2 f3 = __half22float2(*(__half2*)&u.w);
            int d = w * 8;
            o[d+0] += p * f0.x; o[d+1] += p * f0.y;
            o[d+2] += p * f1.x; o[d+3] += p * f1.y;
            o[d+4] += p * f2.x; o[d+5] += p * f2.y;
            o[d+6] += p * f3.x; o[d+7] += p * f3.y;
        }
    };

    for (int j = 0; j < TEXTL; j++)
        accum(j, __half2float(S[i * 192 + j]));
    for (int j = 0; j <= i; j++)
        accum(TEXTL + j, __half2float(S[i * 192 + TEXTL + j]));

    const int tq = TEXTL + xr * 64 + i;
    store_attn_row(o, 1.f / sum, (size_t)(b * NP + tq), h);
}

// ---------------------------------------------------------------------------
// Launch
// ---------------------------------------------------------------------------
extern "C" void kernel_launch(void* const* d_in, const int* in_sizes, int n_in,
                              void* d_out, int out_size)
{
    const float* x     = nullptr;
    const void*  mask  = nullptr;
    const float* w_qkv = nullptr;
    const float* w_out = nullptr;
    for (int i = 0; i < n_in; i++) {
        long long sz = in_sizes[i];
        if      (sz == (long long)BATCH * NSEQ * DIMC) x     = (const float*)d_in[i];
        else if (sz == BATCH * TEXTL)                  mask  = d_in[i];
        else if (sz == (long long)DIMC * TRIPLE)       w_qkv = (const float*)d_in[i];
        else if (sz == (long long)DIMC * DIMC)         w_out = (const float*)d_in[i];
    }
    float* out = (float*)d_out;

    __half *ah, *al, *bq, *bo;
    float *qkv;
    cudaGetSymbolAddress((void**)&ah, g_ah);
    cudaGetSymbolAddress((void**)&al, g_al);
    cudaGetSymbolAddress((void**)&bq, g_b_qkv);
    cudaGetSymbolAddress((void**)&bo, g_b_out);
    cudaGetSymbolAddress((void**)&qkv, g_qkv);

    const int SMEM_TXT = 98304;
    cudaFuncSetAttribute(text_attn_kernel, cudaFuncAttributeMaxDynamicSharedMemorySize, SMEM_TXT);
    cudaFuncSetAttribute(img_attn_kernel,  cudaFuncAttributeMaxDynamicSharedMemorySize, SMEM_IMG);
    cudaFuncSetAttribute(gemm_fp16x2_kernel<TRIPLE, false>,
                         cudaFuncAttributeMaxDynamicSharedMemorySize, SMEM_GEMM);
    cudaFuncSetAttribute(gemm_fp16x2_kernel<DIMC, true>,
                         cudaFuncAttributeMaxDynamicSharedMemorySize, SMEM_GEMM);

    normalize_mask_kernel<<<1, 256>>>(mask);
    conv_w_kernel<<<dim3(TRIPLE / 32, KTOT / 32), dim3(32, 8)>>>(w_qkv, bq, KTOT, TRIPLE);
    conv_w_kernel<<<dim3(DIMC / 32,   KTOT / 32), dim3(32, 8)>>>(w_out, bo, KTOT, DIMC);
    split_a_kernel<<<MROWS, 256>>>(x);

    dim3 g1(TRIPLE / 128, MROWS / 128);  // 24 x 264
    gemm_fp16x2_kernel<TRIPLE, false><<<g1, 256, SMEM_GEMM>>>(ah, al, bq, qkv);

    text_attn_kernel<<<BATCH * NHEAD, 128, SMEM_TXT>>>();
    img_attn_kernel<<<BATCH * NHEAD * IMGDIM, 64, SMEM_IMG>>>();

    dim3 g2(DIMC / 128, MROWS / 128);    // 8 x 264
    gemm_fp16x2_kernel<DIMC, true><<<g2, 256, SMEM_GEMM>>>(ah, al, bo, out);
}

// round 8
// speedup vs baseline: 3.6061x; 1.8995x over previous
#include <cuda_runtime.h>
#include <cuda_fp16.h>
#include <float.h>
#include <stdint.h>

// ---------------------------------------------------------------------------
// Problem constants
// ---------------------------------------------------------------------------
#define BATCH   8
#define NP      4224
#define NSEQ    4223
#define TEXTL   128
#define IMGDIM  64
#define NHEAD   16
#define DHEAD   64
#define DIMC    1024
#define TRIPLE  3072
#define MROWS   (BATCH*NP)    // 33792
#define KTOT    1024
#define BK      32
#define NCHUNK  (KTOT / BK)

// Scratch (device globals — no allocation allowed)
__device__ float   g_qkv  [(size_t)BATCH * NP * TRIPLE];
__device__ __half  g_ah   [(size_t)MROWS * KTOT];     // A hi (x, then attn out)
__device__ __half  g_al   [(size_t)MROWS * KTOT];     // A lo
__device__ __half  g_b_qkv[(size_t)TRIPLE * KTOT];    // w_qkv^T fp16
__device__ __half  g_b_out[(size_t)DIMC * KTOT];      // w_out^T fp16
__device__ uint8_t g_mask [BATCH * TEXTL];

// ---------------------------------------------------------------------------
// PTX helpers (baseline PTX only — compute_103 virtual arch)
// ---------------------------------------------------------------------------
__device__ __forceinline__ uint32_t smem_u32(const void* p) {
    uint32_t a;
    asm("{ .reg .u64 t; cvta.to.shared.u64 t, %1; cvt.u32.u64 %0, t; }" : "=r"(a) : "l"(p));
    return a;
}
__device__ __forceinline__ void mma16816(float d[4],
    uint32_t a0, uint32_t a1, uint32_t a2, uint32_t a3, uint32_t b0, uint32_t b1)
{
    asm volatile(
        "mma.sync.aligned.m16n8k16.row.col.f32.f16.f16.f32 "
        "{%0,%1,%2,%3},{%4,%5,%6,%7},{%8,%9},{%0,%1,%2,%3};\n"
        : "+f"(d[0]), "+f"(d[1]), "+f"(d[2]), "+f"(d[3])
        : "r"(a0), "r"(a1), "r"(a2), "r"(a3), "r"(b0), "r"(b1));
}
__device__ __forceinline__ void ldsm_x4(uint32_t r[4], uint32_t addr)
{
    asm volatile("ldmatrix.sync.aligned.m8n8.x4.shared.b16 {%0,%1,%2,%3}, [%4];"
                 : "=r"(r[0]), "=r"(r[1]), "=r"(r[2]), "=r"(r[3]) : "r"(addr));
}
__device__ __forceinline__ void ldsm_x4_t(uint32_t r[4], uint32_t addr)
{
    asm volatile("ldmatrix.sync.aligned.m8n8.x4.trans.shared.b16 {%0,%1,%2,%3}, [%4];"
                 : "=r"(r[0]), "=r"(r[1]), "=r"(r[2]), "=r"(r[3]) : "r"(addr));
}
__device__ __forceinline__ void ldsm_x2_t(uint32_t r[2], uint32_t addr)
{
    asm volatile("ldmatrix.sync.aligned.m8n8.x2.trans.shared.b16 {%0,%1}, [%2];"
                 : "=r"(r[0]), "=r"(r[1]) : "r"(addr));
}
__device__ __forceinline__ uint32_t pack_f16x2(float lo, float hi)
{
    uint32_t r;
    asm("cvt.rn.f16x2.f32 %0, %1, %2;" : "=r"(r) : "f"(hi), "f"(lo));
    return r;
}
__device__ __forceinline__ uint32_t ex2_f16x2(uint32_t h)
{
    uint32_t r;
    asm("ex2.approx.f16x2 %0, %1;" : "=r"(r) : "r"(h));
    return r;
}
__device__ __forceinline__ void cp_async16(uint32_t dst, const void* src)
{
    asm volatile("cp.async.cg.shared.global [%0], [%1], 16;" :: "r"(dst), "l"(src) : "memory");
}
#define CP_COMMIT()  asm volatile("cp.async.commit_group;" ::: "memory")
#define CP_WAIT(N)   asm volatile("cp.async.wait_group %0;" :: "n"(N) : "memory")

// ---------------------------------------------------------------------------
// Mask normalization (bool mask may arrive as int32 / float32 / uint8)
// ---------------------------------------------------------------------------
__global__ void normalize_mask_kernel(const void* __restrict__ mask_raw)
{
    __shared__ int cls;
    const uint32_t* w = (const uint32_t*)mask_raw;
    const uint8_t*  c = (const uint8_t*)mask_raw;
    if (threadIdx.x == 0) {
        bool all_int = true, all_f32 = true;
        for (int i = 0; i < 256; i++) {
            uint32_t v = w[i];
            if (v != 0u && v != 1u)          all_int = false;
            if (v != 0u && v != 0x3F800000u) all_f32 = false;
        }
        cls = (all_int || all_f32) ? 0 : 1;
    }
    __syncthreads();
    for (int i = threadIdx.x; i < BATCH * TEXTL; i += blockDim.x)
        g_mask[i] = (cls == 0) ? (w[i] != 0u) : (c[i] != 0u);
}

// ---------------------------------------------------------------------------
// fp32 -> (hi, lo) fp16 split
// ---------------------------------------------------------------------------
__device__ __forceinline__ void split1h(float v, __half& h, __half& l)
{
    h = __float2half_rn(v);
    l = __float2half_rn(v - __half2float(h));
}

// A-side split of x (with batch padding): g_ah/g_al [MROWS][KTOT]
__global__ __launch_bounds__(256) void split_a_kernel(const float* __restrict__ src)
{
    int idx = blockIdx.x * 256 + threadIdx.x;
    int m   = idx >> 8;
    int c4  = idx & 255;
    float4 v = make_float4(0.f, 0.f, 0.f, 0.f);
    {
        int b = m / NP, t = m - b * NP;
        if (t < NSEQ) v = *(const float4*)&src[((size_t)(b * NSEQ + t)) * KTOT + c4 * 4];
    }
    __half h[4], l[4];
    split1h(v.x, h[0], l[0]); split1h(v.y, h[1], l[1]);
    split1h(v.z, h[2], l[2]); split1h(v.w, h[3], l[3]);
    size_t off = (size_t)m * KTOT + c4 * 4;
    *(uint2*)&g_ah[off] = *(uint2*)h;
    *(uint2*)&g_al[off] = *(uint2*)l;
}

// W-side: transpose + single-round fp16.  src [K][C] fp32 -> dst [C][K] fp16
__global__ __launch_bounds__(256) void conv_w_kernel(
    const float* __restrict__ src, __half* __restrict__ dst, int K, int C)
{
    __shared__ float tile[32][33];
    int c0 = blockIdx.x * 32, k0 = blockIdx.y * 32;
    int x = threadIdx.x, y = threadIdx.y;
#pragma unroll
    for (int i = 0; i < 32; i += 8)
        tile[y + i][x] = src[(size_t)(k0 + y + i) * C + c0 + x];
    __syncthreads();
#pragma unroll
    for (int i = 0; i < 32; i += 8)
        dst[(size_t)(c0 + y + i) * K + k0 + x] = __float2half_rn(tile[x][y + i]);
}

// ---------------------------------------------------------------------------
// fp16x2 tensor-core GEMM (unchanged from R7)
// ---------------------------------------------------------------------------
#define LSTRIDE   40
#define ARR_ELEMS (128 * LSTRIDE)
#define STAGE_ELEMS (3 * ARR_ELEMS)
#define SMEM_GEMM (2 * STAGE_ELEMS * 2)

template <int NSTRIDE, bool TRIM>
__global__ __launch_bounds__(256, 2)
void gemm_fp16x2_kernel(const __half* __restrict__ Ahg,
                        const __half* __restrict__ Alg,
                        const __half* __restrict__ Bg,
                        float* __restrict__ C)
{
    extern __shared__ __half sm[];
    const int tid  = threadIdx.x;
    const int bn   = blockIdx.x;
    const int bm   = blockIdx.y;
    const int warp = tid >> 5;
    const int lane = tid & 31;
    const int wm   = warp >> 2;
    const int wn   = warp & 3;
    const int g    = lane >> 2;
    const int t4   = lane & 3;

    float acc[4][4][4];
#pragma unroll
    for (int mi = 0; mi < 4; mi++)
#pragma unroll
        for (int ni = 0; ni < 4; ni++)
#pragma unroll
            for (int r = 0; r < 4; r++) acc[mi][ni][r] = 0.f;

    const int ld_row = tid >> 1;
    const int ld_seg = (tid & 1) * 2;
    const __half* srcAh = Ahg + ((size_t)bm * 128 + ld_row) * KTOT + ld_seg * 8;
    const __half* srcAl = Alg + ((size_t)bm * 128 + ld_row) * KTOT + ld_seg * 8;
    const __half* srcB  = Bg  + ((size_t)bn * 128 + ld_row) * KTOT + ld_seg * 8;
    const uint32_t sm_row = smem_u32(sm) + (ld_row * LSTRIDE + ld_seg * 8) * 2;

    auto issue = [&](int kc) {
        const int buf = kc & 1;
        const int k0  = kc * BK;
        uint32_t dst = sm_row + buf * (STAGE_ELEMS * 2);
        cp_async16(dst,                          srcAh + k0);
        cp_async16(dst + 16,                     srcAh + k0 + 8);
        cp_async16(dst + ARR_ELEMS * 2,          srcAl + k0);
        cp_async16(dst + ARR_ELEMS * 2 + 16,     srcAl + k0 + 8);
        cp_async16(dst + 2 * ARR_ELEMS * 2,      srcB  + k0);
        cp_async16(dst + 2 * ARR_ELEMS * 2 + 16, srcB  + k0 + 8);
        CP_COMMIT();
    };

    issue(0);

    const uint32_t smem0 = smem_u32(sm);
    const int a_row_off = (wm * 64 + (lane & 15)) * 80 + (lane >> 4) * 16;
    const int b_row_off = (wn * 32 + ((lane >> 4) << 3) + (lane & 7)) * 80
                        + ((lane >> 3) & 1) * 16;

    for (int kc = 0; kc < NCHUNK; kc++) {
        const int buf = kc & 1;
        if (kc + 1 < NCHUNK) { issue(kc + 1); CP_WAIT(1); }
        else                 { CP_WAIT(0); }
        __syncthreads();

        const uint32_t base = smem0 + buf * (STAGE_ELEMS * 2);
        const uint32_t aAh = base;
        const uint32_t aAl = base + ARR_ELEMS * 2;
        const uint32_t aB  = base + 2 * ARR_ELEMS * 2;

#pragma unroll
        for (int ks = 0; ks < 2; ks++) {
            const int kb = ks * 32;
            uint32_t bf[2][4];
#pragma unroll
            for (int nip = 0; nip < 2; nip++)
                ldsm_x4(bf[nip], aB + b_row_off + nip * (16 * 80) + kb);
#pragma unroll
            for (int mi = 0; mi < 4; mi++) {
                uint32_t ah[4], al[4];
                ldsm_x4(ah, aAh + a_row_off + mi * (16 * 80) + kb);
                ldsm_x4(al, aAl + a_row_off + mi * (16 * 80) + kb);
#pragma unroll
                for (int nip = 0; nip < 2; nip++) {
#pragma unroll
                    for (int s = 0; s < 2; s++) {
                        int ni = nip * 2 + s;
                        uint32_t b0 = bf[nip][2*s], b1 = bf[nip][2*s+1];
                        mma16816(acc[mi][ni], ah[0],ah[1],ah[2],ah[3], b0,b1);
                        mma16816(acc[mi][ni], al[0],al[1],al[2],al[3], b0,b1);
                    }
                }
            }
        }
        __syncthreads();
    }

#pragma unroll
    for (int mi = 0; mi < 4; mi++) {
#pragma unroll
        for (int half = 0; half < 2; half++) {
            int m = bm * 128 + wm * 64 + mi * 16 + g + half * 8;
            float* dst = nullptr;
            if (TRIM) {
                int b = m / NP, t = m - b * NP;
                if (t < NSEQ) dst = &C[((size_t)(b * NSEQ + t)) * NSTRIDE];
            } else {
                dst = &C[(size_t)m * NSTRIDE];
            }
            if (dst) {
                int ncol = bn * 128 + wn * 32 + t4 * 2;
#pragma unroll
                for (int ni = 0; ni < 4; ni++) {
                    float2 v = make_float2(acc[mi][ni][half * 2], acc[mi][ni][half * 2 + 1]);
                    *(float2*)&dst[ncol + ni * 8] = v;
                }
            }
        }
    }
}

// ---------------------------------------------------------------------------
// Attention epilogue helper: write o*inv as fp16 hi/lo into g_ah/g_al
// ---------------------------------------------------------------------------
__device__ __forceinline__ void store_attn_row(
    const float* o, float inv, size_t row, int h)
{
    size_t off = row * KTOT + h * DHEAD;
#pragma unroll
    for (int d = 0; d < 64; d += 2) {
        float v0 = o[d] * inv, v1 = o[d + 1] * inv;
        __half h0, l0, h1, l1;
        split1h(v0, h0, l0);
        split1h(v1, h1, l1);
        *(__half2*)&g_ah[off + d] = __halves2half2(h0, h1);
        *(__half2*)&g_al[off + d] = __halves2half2(l0, l1);
    }
}

// ---------------------------------------------------------------------------
// Text attention: per (b,h), 128 queries x 128 keys, causal. fp32.
// ---------------------------------------------------------------------------
__global__ __launch_bounds__(128) void text_attn_kernel()
{
    extern __shared__ float smf[];
    float* KV = smf;
    float* S  = smf + 128 * 64;

    const int bh = blockIdx.x;
    const int b  = bh / NHEAD;
    const int h  = bh - b * NHEAD;
    const int i  = threadIdx.x;

    for (int idx = threadIdx.x; idx < 128 * 64 / 4; idx += 128) {
        int t = idx >> 4, c4 = idx & 15;
        *(float4*)&KV[t * 64 + c4 * 4] =
            *(const float4*)&g_qkv[((size_t)(b * NP + t)) * TRIPLE + DIMC + h * DHEAD + c4 * 4];
    }
    __syncthreads();

    float q[64];
    {
        const float* qp = &g_qkv[((size_t)(b * NP + i)) * TRIPLE + h * DHEAD];
#pragma unroll
        for (int d = 0; d < 64; d++) q[d] = qp[d] * 0.125f;
    }

    float mx = -FLT_MAX;
    for (int j = 0; j <= i; j++) {
        const float* kp = &KV[j * 64];
        float s0 = 0.f, s1 = 0.f, s2 = 0.f, s3 = 0.f;
#pragma unroll
        for (int d = 0; d < 64; d += 4) {
            s0 += q[d+0] * kp[d+0]; s1 += q[d+1] * kp[d+1];
            s2 += q[d+2] * kp[d+2]; s3 += q[d+3] * kp[d+3];
        }
        float s = (s0 + s1) + (s2 + s3);
        S[i * 128 + j] = s;
        mx = fmaxf(mx, s);
    }
    float sum = 0.f;
    for (int j = 0; j <= i; j++) {
        float p = __expf(S[i * 128 + j] - mx);
        S[i * 128 + j] = p;
        sum += p;
    }
    __syncthreads();

    for (int idx = threadIdx.x; idx < 128 * 64 / 4; idx += 128) {
        int t = idx >> 4, c4 = idx & 15;
        *(float4*)&KV[t * 64 + c4 * 4] =
            *(const float4*)&g_qkv[((size_t)(b * NP + t)) * TRIPLE + 2 * DIMC + h * DHEAD + c4 * 4];
    }
    __syncthreads();

    float o[64];
#pragma unroll
    for (int d = 0; d < 64; d++) o[d] = 0.f;
    for (int j = 0; j <= i; j++) {
        float p = S[i * 128 + j];
        const float* vp = &KV[j * 64];
#pragma unroll
        for (int d = 0; d < 64; d++) o[d] += p * vp[d];
    }
    store_attn_row(o, 1.f / sum, (size_t)(b * NP + i), h);
}

// ---------------------------------------------------------------------------
// Image (axial) attention — tensor-core version.
// Block = 128 threads (4 warps) per (b,h,imgrow). Warp w owns 16 query rows.
// S = Q·K^T via m16n8k16 (24 n-tiles); softmax in registers with
// D->A fragment reuse (exp via ex2.approx.f16x2); PV with a ones-column in V
// producing the row sums in the 9th output tile.
// ---------------------------------------------------------------------------
#define ISTR 72                                   // fp16 elems per smem row (144B)
#define SMEM_IMG ((64 + 192 + 192) * ISTR * 2 + 128)

__global__ __launch_bounds__(128) void img_attn_kernel()
{
    extern __shared__ __half sh[];
    __half*  Qs = sh;                        // 64 x 72
    __half*  Ks = sh + 64 * ISTR;            // 192 x 72
    __half*  Vs = sh + (64 + 192) * ISTR;    // 192 x 72 (cols 64..71 = ones)
    uint8_t* smask = (uint8_t*)(sh + (64 + 192 + 192) * ISTR);

    const int bid  = blockIdx.x;
    const int xr   = bid & 63;
    const int h    = (bid >> 6) & 15;
    const int b    = bid >> 10;
    const int tid  = threadIdx.x;
    const int warp = tid >> 5;
    const int lane = tid & 31;
    const int g    = lane >> 2;
    const int t4   = lane & 3;

    // ---- loads: Q (scaled), K, V fp32 -> fp16 smem ----
    for (int idx = tid; idx < 64 * 16; idx += 128) {
        int r = idx >> 4, c4 = idx & 15;
        int tq = TEXTL + xr * 64 + r;
        float4 v = *(const float4*)&g_qkv[((size_t)(b * NP + tq)) * TRIPLE + h * DHEAD + c4 * 4];
        __half2* dst = (__half2*)&Qs[r * ISTR + c4 * 4];
        dst[0] = __floats2half2_rn(v.x * 0.125f, v.y * 0.125f);
        dst[1] = __floats2half2_rn(v.z * 0.125f, v.w * 0.125f);
    }
    for (int idx = tid; idx < 192 * 16; idx += 128) {
        int r = idx >> 4, c4 = idx & 15;
        int t = (r < TEXTL) ? r : (TEXTL + xr * 64 + (r - TEXTL));
        float4 v = *(const float4*)&g_qkv[((size_t)(b * NP + t)) * TRIPLE + DIMC + h * DHEAD + c4 * 4];
        __half2* dst = (__half2*)&Ks[r * ISTR + c4 * 4];
        dst[0] = __floats2half2_rn(v.x, v.y);
        dst[1] = __floats2half2_rn(v.z, v.w);
    }
    for (int idx = tid; idx < 192 * 16; idx += 128) {
        int r = idx >> 4, c4 = idx & 15;
        int t = (r < TEXTL) ? r : (TEXTL + xr * 64 + (r - TEXTL));
        float4 v = *(const float4*)&g_qkv[((size_t)(b * NP + t)) * TRIPLE + 2 * DIMC + h * DHEAD + c4 * 4];
        __half2* dst = (__half2*)&Vs[r * ISTR + c4 * 4];
        dst[0] = __floats2half2_rn(v.x, v.y);
        dst[1] = __floats2half2_rn(v.z, v.w);
    }
    for (int idx = tid; idx < 192 * 4; idx += 128) {       // ones cols 64..71
        int r = idx >> 2, c = (idx & 3) * 2;
        *(__half2*)&Vs[r * ISTR + 64 + c] = __floats2half2_rn(1.f, 1.f);
    }
    for (int j = tid; j < TEXTL; j += 128) smask[j] = g_mask[b * TEXTL + j];
    __syncthreads();

    // ---- S = Q K^T : 24 n8-tiles ----
    float s_acc[24][4];
#pragma unroll
    for (int jt = 0; jt < 24; jt++)
#pragma unroll
        for (int r = 0; r < 4; r++) s_acc[jt][r] = 0.f;

    const uint32_t qbase = smem_u32(Qs) + (warp * 16 + (lane & 15)) * 144 + (lane >> 4) * 16;
    const uint32_t kbase = smem_u32(Ks) + (((lane >> 4) << 3) + (lane & 7)) * 144
                         + ((lane >> 3) & 1) * 16;
#pragma unroll
    for (int ks = 0; ks < 4; ks++) {
        uint32_t af[4];
        ldsm_x4(af, qbase + ks * 32);
#pragma unroll
        for (int jp = 0; jp < 12; jp++) {
            uint32_t bf[4];
            ldsm_x4(bf, kbase + jp * (16 * 144) + ks * 32);
            mma16816(s_acc[2*jp],   af[0],af[1],af[2],af[3], bf[0],bf[1]);
            mma16816(s_acc[2*jp+1], af[0],af[1],af[2],af[3], bf[2],bf[3]);
        }
    }

    // ---- masking ----
    const int rq0 = warp * 16 + g;     // query row (0..63), row g
    const int rq1 = rq0 + 8;           // row g+8
#pragma unroll
    for (int jt = 0; jt < 16; jt++) {  // text keys
        int c = jt * 8 + 2 * t4;
        if (!smask[c])   { s_acc[jt][0] = -1e30f; s_acc[jt][2] = -1e30f; }
        if (!smask[c+1]) { s_acc[jt][1] = -1e30f; s_acc[jt][3] = -1e30f; }
    }
#pragma unroll
    for (int jt = 16; jt < 24; jt++) { // causal row keys
        int c = (jt - 16) * 8 + 2 * t4;
        if (c     > rq0) s_acc[jt][0] = -1e30f;
        if (c + 1 > rq0) s_acc[jt][1] = -1e30f;
        if (c     > rq1) s_acc[jt][2] = -1e30f;
        if (c + 1 > rq1) s_acc[jt][3] = -1e30f;
    }

    // ---- row max across the 4 lanes of each row (t4 butterfly) ----
    float mx0 = -1e30f, mx1 = -1e30f;
#pragma unroll
    for (int jt = 0; jt < 24; jt++) {
        mx0 = fmaxf(mx0, fmaxf(s_acc[jt][0], s_acc[jt][1]));
        mx1 = fmaxf(mx1, fmaxf(s_acc[jt][2], s_acc[jt][3]));
    }
    mx0 = fmaxf(mx0, __shfl_xor_sync(0xffffffffu, mx0, 1));
    mx0 = fmaxf(mx0, __shfl_xor_sync(0xffffffffu, mx0, 2));
    mx1 = fmaxf(mx1, __shfl_xor_sync(0xffffffffu, mx1, 1));
    mx1 = fmaxf(mx1, __shfl_xor_sync(0xffffffffu, mx1, 2));

    // ---- P = exp(S - mx) packed fp16 (A-fragment layout) ----
    const float L2E = 1.44269504f;
    const float c0 = mx0 * L2E, c1 = mx1 * L2E;
    uint32_t p_lo[24], p_hi[24];
#pragma unroll
    for (int jt = 0; jt < 24; jt++) {
        float f0 = fmaf(s_acc[jt][0], L2E, -c0);
        float f1 = fmaf(s_acc[jt][1], L2E, -c0);
        float f2 = fmaf(s_acc[jt][2], L2E, -c1);
        float f3 = fmaf(s_acc[jt][3], L2E, -c1);
        p_lo[jt] = ex2_f16x2(pack_f16x2(f0, f1));
        p_hi[jt] = ex2_f16x2(pack_f16x2(f2, f3));
    }

    // ---- O = P V  (9 n-tiles; tile 8 = ones column -> row sums) ----
    float o[9][4];
#pragma unroll
    for (int nt = 0; nt < 9; nt++)
#pragma unroll
        for (int r = 0; r < 4; r++) o[nt][r] = 0.f;

    const uint32_t vbase = smem_u32(Vs) + ((((lane >> 3) & 1) * 8) + (lane & 7)) * 144
                         + (lane >> 4) * 16;
    const uint32_t vones = smem_u32(Vs) + ((((lane >> 3) & 1) * 8) + (lane & 7)) * 144 + 128;
#pragma unroll
    for (int kt = 0; kt < 12; kt++) {
        uint32_t a0 = p_lo[2*kt], a1 = p_hi[2*kt], a2 = p_lo[2*kt+1], a3 = p_hi[2*kt+1];
#pragma unroll
        for (int np = 0; np < 4; np++) {
            uint32_t bf[4];
            ldsm_x4_t(bf, vbase + kt * (16 * 144) + np * 32);
            mma16816(o[2*np],   a0,a1,a2,a3, bf[0],bf[1]);
            mma16816(o[2*np+1], a0,a1,a2,a3, bf[2],bf[3]);
        }
        uint32_t bo[2];
        ldsm_x2_t(bo, vones + kt * (16 * 144));
        mma16816(o[8], a0,a1,a2,a3, bo[0],bo[1]);
    }

    // ---- epilogue: divide by sum, split fp16 hi/lo into g_ah/g_al ----
    const float inv0 = 1.f / o[8][0];
    const float inv1 = 1.f / o[8][2];
    const size_t row0 = ((size_t)(b * NP + TEXTL + xr * 64 + rq0)) * KTOT + h * DHEAD;
    const size_t row1 = row0 + 8 * KTOT;
#pragma unroll
    for (int nt = 0; nt < 8; nt++) {
        int c = nt * 8 + 2 * t4;
        __half h0, l0, h1, l1;
        split1h(o[nt][0] * inv0, h0, l0);
        split1h(o[nt][1] * inv0, h1, l1);
        *(__half2*)&g_ah[row0 + c] = __halves2half2(h0, h1);
        *(__half2*)&g_al[row0 + c] = __halves2half2(l0, l1);
        split1h(o[nt][2] * inv1, h0, l0);
        split1h(o[nt][3] * inv1, h1, l1);
        *(__half2*)&g_ah[row1 + c] = __halves2half2(h0, h1);
        *(__half2*)&g_al[row1 + c] = __halves2half2(l0, l1);
    }
}

// ---------------------------------------------------------------------------
// Launch
// ---------------------------------------------------------------------------
extern "C" void kernel_launch(void* const* d_in, const int* in_sizes, int n_in,
                              void* d_out, int out_size)
{
    const float* x     = nullptr;
    const void*  mask  = nullptr;
    const float* w_qkv = nullptr;
    const float* w_out = nullptr;
    for (int i = 0; i < n_in; i++) {
        long long sz = in_sizes[i];
        if      (sz == (long long)BATCH * NSEQ * DIMC) x     = (const float*)d_in[i];
        else if (sz == BATCH * TEXTL)                  mask  = d_in[i];
        else if (sz == (long long)DIMC * TRIPLE)       w_qkv = (const float*)d_in[i];
        else if (sz == (long long)DIMC * DIMC)         w_out = (const float*)d_in[i];
    }
    float* out = (float*)d_out;

    __half *ah, *al, *bq, *bo;
    float *qkv;
    cudaGetSymbolAddress((void**)&ah, g_ah);
    cudaGetSymbolAddress((void**)&al, g_al);
    cudaGetSymbolAddress((void**)&bq, g_b_qkv);
    cudaGetSymbolAddress((void**)&bo, g_b_out);
    cudaGetSymbolAddress((void**)&qkv, g_qkv);

    const int SMEM_TXT = 98304;
    cudaFuncSetAttribute(text_attn_kernel, cudaFuncAttributeMaxDynamicSharedMemorySize, SMEM_TXT);
    cudaFuncSetAttribute(img_attn_kernel,  cudaFuncAttributeMaxDynamicSharedMemorySize, SMEM_IMG);
    cudaFuncSetAttribute(gemm_fp16x2_kernel<TRIPLE, false>,
                         cudaFuncAttributeMaxDynamicSharedMemorySize, SMEM_GEMM);
    cudaFuncSetAttribute(gemm_fp16x2_kernel<DIMC, true>,
                         cudaFuncAttributeMaxDynamicSharedMemorySize, SMEM_GEMM);

    normalize_mask_kernel<<<1, 256>>>(mask);
    conv_w_kernel<<<dim3(TRIPLE / 32, KTOT / 32), dim3(32, 8)>>>(w_qkv, bq, KTOT, TRIPLE);
    conv_w_kernel<<<dim3(DIMC / 32,   KTOT / 32), dim3(32, 8)>>>(w_out, bo, KTOT, DIMC);
    split_a_kernel<<<MROWS, 256>>>(x);

    dim3 g1(TRIPLE / 128, MROWS / 128);  // 24 x 264
    gemm_fp16x2_kernel<TRIPLE, false><<<g1, 256, SMEM_GEMM>>>(ah, al, bq, qkv);

    text_attn_kernel<<<BATCH * NHEAD, 128, SMEM_TXT>>>();
    img_attn_kernel<<<BATCH * NHEAD * IMGDIM, 128, SMEM_IMG>>>();

    dim3 g2(DIMC / 128, MROWS / 128);    // 8 x 264
    gemm_fp16x2_kernel<DIMC, true><<<g2, 256, SMEM_GEMM>>>(ah, al, bo, out);
}